// round 4
// baseline (speedup 1.0000x reference)
#include <cuda_runtime.h>
#include <cstdint>
#include <cstddef>

// Problem dims
#define BB   4
#define LL   4096
#define DIMM 2048
#define SS   128
#define MM   (BB*LL)        // 16384 token rows
#define N1   512            // dt | Bx_re | Bx_im | pg
#define K1   6144           // xr(2048) | xi(2048) | cab(2048)
#define K2   256            // hr(128) | hi(128)
#define N2   4096           // interleaved (yr,yi) per d
#define NC   64             // scan chunks per lane
#define CHUNK (LL/NC)       // 64

// smem tile sizes (floats), BLOCK_M=128, BLOCK_N=128, BLOCK_K=32
#define ASZ (128*36)        // A tile [m][k], pad 36 -> conflict free frag loads
#define BSZ (32*136)        // B tile [k][n], pad 136 -> conflict free frag loads

// -------- scratch (no allocations allowed; __device__ globals) --------
__device__ float  g_W1[(size_t)K1*N1];      // packed weights for GEMM1 (tf32-rounded)
__device__ float  g_G1[(size_t)MM*N1];      // GEMM1 raw outputs
__device__ float4 g_ABx[(size_t)MM*SS];     // {Ar,Ai,Bxr,Bxi} per (m,s)
__device__ float2 g_cA[BB*NC*SS];           // chunk A-products
__device__ float2 g_cH[BB*NC*SS];           // chunk local h_end
__device__ float2 g_carry[BB*NC*SS];        // per-chunk carry-in
__device__ float  g_H[(size_t)MM*K2];       // [hr|hi] rows for GEMM2
__device__ float  g_W2[(size_t)K2*N2];      // packed weights for GEMM2 (tf32-rounded)

__device__ __forceinline__ float to_tf32(float v){
    unsigned u; asm("cvt.rna.tf32.f32 %0, %1;" : "=r"(u) : "f"(v));
    return __uint_as_float(u);
}

__device__ __forceinline__ void mma8(float* c, const unsigned* a, const unsigned* b){
    asm volatile(
        "mma.sync.aligned.m16n8k8.row.col.f32.tf32.tf32.f32 "
        "{%0,%1,%2,%3}, {%4,%5,%6,%7}, {%8,%9}, {%0,%1,%2,%3};\n"
        : "+f"(c[0]), "+f"(c[1]), "+f"(c[2]), "+f"(c[3])
        : "r"(a[0]), "r"(a[1]), "r"(a[2]), "r"(a[3]), "r"(b[0]), "r"(b[1]));
}

// ---------------- weight packing ----------------
// W1[k, n], n<128: dt_w; n in [128,256): Bx real; [256,384): Bx imag; [384,512): pg
__global__ void prep_w1(const float* __restrict__ dt_w, const float* __restrict__ Br,
                        const float* __restrict__ Bi,   const float* __restrict__ pg_w){
    int idx = blockIdx.x*256 + threadIdx.x;
    int n = idx & (N1-1);
    int k = idx >> 9;
    float v = 0.f;
    if (n < 128) {
        if (k < 4096) v = dt_w[(size_t)n*4096 + k];
    } else if (n < 256) {
        int s = n - 128;
        if (k < 2048)       v =  Br[(size_t)k*SS + s];
        else if (k < 4096)  v = -Bi[(size_t)(k-2048)*SS + s];
    } else if (n < 384) {
        int s = n - 256;
        if (k < 2048)       v =  Bi[(size_t)k*SS + s];
        else if (k < 4096)  v =  Br[(size_t)(k-2048)*SS + s];
    } else {
        int s = n - 384;
        if (k >= 4096)      v =  pg_w[(size_t)s*DIMM + (k-4096)];
    }
    g_W1[idx] = to_tf32(v);
}

// W2[k, n] with n = 2d+c: k<128 (hr): c? Ci : Cr ; k>=128 (hi): c? Cr : -Ci
__global__ void prep_w2(const float* __restrict__ Cr, const float* __restrict__ Ci){
    int idx = blockIdx.x*256 + threadIdx.x;
    int n = idx & (N2-1);
    int k = idx >> 12;
    int d = n >> 1, c = n & 1;
    float v;
    if (k < 128) v = c ? Ci[(size_t)k*DIMM + d] : Cr[(size_t)k*DIMM + d];
    else { int s = k - 128; v = c ? Cr[(size_t)s*DIMM + d] : -Ci[(size_t)s*DIMM + d]; }
    g_W2[idx] = to_tf32(v);
}

// ---------------- GEMM1: projections ----------------
// grid: blockIdx = mt*4 + nb; nb in {0,1,2}: K range [0,4096) over [xr|xi];
// nb==3: K range [4096,6144) over cab (computed on the fly).
__global__ __launch_bounds__(256,1) void gemm1(const float* __restrict__ x){
    extern __shared__ float smem[];
    float* As = smem;
    float* Bs = smem + 2*ASZ;

    const int tid = threadIdx.x;
    const int nb  = blockIdx.x & 3;
    const int mt  = blockIdx.x >> 2;
    const int kstart = (nb < 3) ? 0 : 4096;
    const int KT     = (nb < 3) ? 128 : 64;

    const int am = tid >> 3;            // A row 0..31 (+32j)
    const int ak = (tid & 7) << 2;      // A k 0..28
    const int bk = tid >> 5;            // B k 0..7 (+8j)
    const int bn = (tid & 31) << 2;     // B n 0..124

    const int lane = tid & 31;
    const int warp = tid >> 5;
    const int wm = (warp >> 1) * 32;    // 4 warps in M
    const int wn = (warp & 1) * 64;     // 2 warps in N
    const int g = lane >> 2;
    const int t = lane & 3;

    float acc[2][8][4];
    #pragma unroll
    for (int mi=0;mi<2;mi++){ 
        #pragma unroll
        for (int ni=0;ni<8;ni++){ acc[mi][ni][0]=0.f; acc[mi][ni][1]=0.f; acc[mi][ni][2]=0.f; acc[mi][ni][3]=0.f; }
    }

    float sa[16], sb[16];

    auto LOADT = [&](int kt){
        const int k0 = kstart + kt*32;
        const int kg = k0 + ak;
        const int d  = (kg < 2048) ? kg : ((kg < 4096) ? kg - 2048 : kg - 4096);
        #pragma unroll
        for (int j=0;j<4;j++){
            int row = mt*128 + am + 32*j;
            const float4* p = reinterpret_cast<const float4*>(x + ((size_t)row*DIMM + d)*2);
            float4 u = p[0], v4 = p[1];
            if (kg < 2048){
                sa[j*4+0]=u.x; sa[j*4+1]=u.z; sa[j*4+2]=v4.x; sa[j*4+3]=v4.z;
            } else if (kg < 4096){
                sa[j*4+0]=u.y; sa[j*4+1]=u.w; sa[j*4+2]=v4.y; sa[j*4+3]=v4.w;
            } else {
                sa[j*4+0]=sqrtf(u.x*u.x+u.y*u.y);
                sa[j*4+1]=sqrtf(u.z*u.z+u.w*u.w);
                sa[j*4+2]=sqrtf(v4.x*v4.x+v4.y*v4.y);
                sa[j*4+3]=sqrtf(v4.z*v4.z+v4.w*v4.w);
            }
        }
        #pragma unroll
        for (int j=0;j<16;j++) sa[j] = to_tf32(sa[j]);
        #pragma unroll
        for (int j=0;j<4;j++){
            int kl = bk + 8*j;
            float4 w = *reinterpret_cast<const float4*>(&g_W1[(size_t)(k0+kl)*N1 + nb*128 + bn]);
            sb[j*4+0]=w.x; sb[j*4+1]=w.y; sb[j*4+2]=w.z; sb[j*4+3]=w.w;
        }
    };
    auto STORET = [&](int buf){
        float* Ab = As + buf*ASZ;
        float* Bb = Bs + buf*BSZ;
        #pragma unroll
        for (int j=0;j<4;j++)
            *reinterpret_cast<float4*>(&Ab[(am+32*j)*36 + ak]) =
                make_float4(sa[j*4],sa[j*4+1],sa[j*4+2],sa[j*4+3]);
        #pragma unroll
        for (int j=0;j<4;j++)
            *reinterpret_cast<float4*>(&Bb[(bk+8*j)*136 + bn]) =
                make_float4(sb[j*4],sb[j*4+1],sb[j*4+2],sb[j*4+3]);
    };
    auto COMPUTE = [&](int buf){
        const float* Ab = As + buf*ASZ;
        const float* Bb = Bs + buf*BSZ;
        #pragma unroll
        for (int kk=0;kk<4;kk++){
            const int k = kk*8;
            unsigned af[2][4];
            #pragma unroll
            for (int mi=0;mi<2;mi++){
                int r = wm + mi*16 + g;
                af[mi][0] = __float_as_uint(Ab[r*36 + k + t]);
                af[mi][1] = __float_as_uint(Ab[(r+8)*36 + k + t]);
                af[mi][2] = __float_as_uint(Ab[r*36 + k + t + 4]);
                af[mi][3] = __float_as_uint(Ab[(r+8)*36 + k + t + 4]);
            }
            unsigned bf[8][2];
            #pragma unroll
            for (int ni=0;ni<8;ni++){
                int n = wn + ni*8 + g;
                bf[ni][0] = __float_as_uint(Bb[(k+t)*136 + n]);
                bf[ni][1] = __float_as_uint(Bb[(k+t+4)*136 + n]);
            }
            #pragma unroll
            for (int mi=0;mi<2;mi++)
                #pragma unroll
                for (int ni=0;ni<8;ni++)
                    mma8(acc[mi][ni], af[mi], bf[ni]);
        }
    };

    LOADT(0); STORET(0); __syncthreads();
    int buf = 0;
    for (int kt=0; kt<KT; kt++){
        if (kt+1 < KT) LOADT(kt+1);
        COMPUTE(buf);
        if (kt+1 < KT) STORET(buf^1);
        __syncthreads();
        buf ^= 1;
    }

    #pragma unroll
    for (int mi=0;mi<2;mi++){
        int row = mt*128 + wm + mi*16 + g;
        #pragma unroll
        for (int ni=0;ni<8;ni++){
            int col = nb*128 + wn + ni*8 + t*2;
            *reinterpret_cast<float2*>(&g_G1[(size_t)row*N1 + col])     = make_float2(acc[mi][ni][0], acc[mi][ni][1]);
            *reinterpret_cast<float2*>(&g_G1[(size_t)(row+8)*N1 + col]) = make_float2(acc[mi][ni][2], acc[mi][ni][3]);
        }
    }
}

// ---------------- elementwise: build A, Bx ----------------
__global__ void ew1(const float* __restrict__ dt_b, const float* __restrict__ dt_bias,
                    const float* __restrict__ lAr,  const float* __restrict__ lAi,
                    const float* __restrict__ pg_b){
    __shared__ float s_ear[SS], s_cos[SS], s_sin[SS], s_db[SS], s_pb[SS];
    int tid = threadIdx.x;
    if (tid < SS){
        s_ear[tid] = expf(lAr[tid]);
        float sn, cs; sincosf(lAi[tid], &sn, &cs);
        s_cos[tid]=cs; s_sin[tid]=sn;
        s_db[tid] = dt_b[tid] + dt_bias[tid];
        s_pb[tid] = pg_b[tid];
    }
    __syncthreads();
    size_t idx = (size_t)blockIdx.x*256 + tid;      // over MM*SS
    int s = (int)(idx & 127);
    size_t m = idx >> 7;
    const float* row = &g_G1[m*N1];
    float z  = row[s] + s_db[s];
    float dt = (z > 20.f) ? z : log1pf(expf(z));
    float bxr = row[128+s], bxi = row[256+s];
    float pz  = row[384+s] + s_pb[s];
    float p   = 1.f/(1.f+expf(-pz));
    float am  = expf(-dt * s_ear[s]);
    float omp = 1.f - p;
    float Ar = p + omp*am*s_cos[s];
    float Ai = omp*am*s_sin[s];
    float sc = omp*dt;
    g_ABx[idx] = make_float4(Ar, Ai, bxr*sc, bxi*sc);
}

// ---------------- chunked scan ----------------
__global__ void scan_a(){
    int b = blockIdx.x >> 6;
    int c = blockIdx.x & (NC-1);
    int s = threadIdx.x;
    size_t base = ((size_t)b*LL + (size_t)c*CHUNK)*SS + s;
    float hr=0.f, hi=0.f, pr=1.f, pi=0.f;
    #pragma unroll 4
    for (int i=0;i<CHUNK;i++){
        float4 v = g_ABx[base + (size_t)i*SS];
        float nhr = v.x*hr - v.y*hi + v.z;
        float nhi = v.x*hi + v.y*hr + v.w;
        float npr = v.x*pr - v.y*pi;
        float npi = v.x*pi + v.y*pr;
        hr=nhr; hi=nhi; pr=npr; pi=npi;
    }
    int o = (b*NC + c)*SS + s;
    g_cA[o] = make_float2(pr,pi);
    g_cH[o] = make_float2(hr,hi);
}

__global__ void scan_b(){
    int tid = threadIdx.x;            // 512 = BB*SS
    int b = tid >> 7, s = tid & 127;
    float cr=0.f, ci=0.f;
    for (int c=0;c<NC;c++){
        int o = (b*NC + c)*SS + s;
        g_carry[o] = make_float2(cr,ci);
        float2 a = g_cA[o]; float2 h = g_cH[o];
        float nr  = a.x*cr - a.y*ci + h.x;
        float ni2 = a.x*ci + a.y*cr + h.y;
        cr=nr; ci=ni2;
    }
}

__global__ void scan_c(float* __restrict__ out){
    int b = blockIdx.x >> 6;
    int c = blockIdx.x & (NC-1);
    int s = threadIdx.x;
    int o = (b*NC + c)*SS + s;
    float2 cc = g_carry[o];
    float hr = cc.x, hi = cc.y;
    size_t base  = ((size_t)b*LL + (size_t)c*CHUNK)*SS + s;
    size_t mbase = (size_t)b*LL + (size_t)c*CHUNK;
    for (int i=0;i<CHUNK;i++){
        float4 v = g_ABx[base + (size_t)i*SS];
        float nhr = v.x*hr - v.y*hi + v.z;
        float nhi = v.x*hi + v.y*hr + v.w;
        hr=nhr; hi=nhi;
        size_t m = mbase + i;
        g_H[m*K2 + s]       = hr;
        g_H[m*K2 + 128 + s] = hi;
    }
    if (c == NC-1){
        out[(size_t)MM*N2 + (b*SS + s)*2 + 0] = hr;
        out[(size_t)MM*N2 + (b*SS + s)*2 + 1] = hi;
    }
}

// ---------------- GEMM2: y = [hr|hi] @ W2 + D*x ----------------
__global__ __launch_bounds__(256,1) void gemm2(const float* __restrict__ x,
                                               const float* __restrict__ Dp,
                                               float* __restrict__ out){
    extern __shared__ float smem[];
    float* As = smem;
    float* Bs = smem + 2*ASZ;

    const int tid = threadIdx.x;
    const int nt  = blockIdx.x & 31;
    const int mt  = blockIdx.x >> 5;
    const int KT  = K2/32;   // 8

    const int am = tid >> 3;
    const int ak = (tid & 7) << 2;
    const int bk = tid >> 5;
    const int bn = (tid & 31) << 2;

    const int lane = tid & 31;
    const int warp = tid >> 5;
    const int wm = (warp >> 1) * 32;
    const int wn = (warp & 1) * 64;
    const int g = lane >> 2;
    const int t = lane & 3;

    float acc[2][8][4];
    #pragma unroll
    for (int mi=0;mi<2;mi++){
        #pragma unroll
        for (int ni=0;ni<8;ni++){ acc[mi][ni][0]=0.f; acc[mi][ni][1]=0.f; acc[mi][ni][2]=0.f; acc[mi][ni][3]=0.f; }
    }

    float sa[16], sb[16];

    auto LOADT = [&](int kt){
        const int k0 = kt*32;
        #pragma unroll
        for (int j=0;j<4;j++){
            int row = mt*128 + am + 32*j;
            float4 h4 = *reinterpret_cast<const float4*>(&g_H[(size_t)row*K2 + k0 + ak]);
            sa[j*4+0]=to_tf32(h4.x); sa[j*4+1]=to_tf32(h4.y);
            sa[j*4+2]=to_tf32(h4.z); sa[j*4+3]=to_tf32(h4.w);
        }
        #pragma unroll
        for (int j=0;j<4;j++){
            int kl = bk + 8*j;
            float4 w = *reinterpret_cast<const float4*>(&g_W2[(size_t)(k0+kl)*N2 + nt*128 + bn]);
            sb[j*4+0]=w.x; sb[j*4+1]=w.y; sb[j*4+2]=w.z; sb[j*4+3]=w.w;
        }
    };
    auto STORET = [&](int buf){
        float* Ab = As + buf*ASZ;
        float* Bb = Bs + buf*BSZ;
        #pragma unroll
        for (int j=0;j<4;j++)
            *reinterpret_cast<float4*>(&Ab[(am+32*j)*36 + ak]) =
                make_float4(sa[j*4],sa[j*4+1],sa[j*4+2],sa[j*4+3]);
        #pragma unroll
        for (int j=0;j<4;j++)
            *reinterpret_cast<float4*>(&Bb[(bk+8*j)*136 + bn]) =
                make_float4(sb[j*4],sb[j*4+1],sb[j*4+2],sb[j*4+3]);
    };
    auto COMPUTE = [&](int buf){
        const float* Ab = As + buf*ASZ;
        const float* Bb = Bs + buf*BSZ;
        #pragma unroll
        for (int kk=0;kk<4;kk++){
            const int k = kk*8;
            unsigned af[2][4];
            #pragma unroll
            for (int mi=0;mi<2;mi++){
                int r = wm + mi*16 + g;
                af[mi][0] = __float_as_uint(Ab[r*36 + k + t]);
                af[mi][1] = __float_as_uint(Ab[(r+8)*36 + k + t]);
                af[mi][2] = __float_as_uint(Ab[r*36 + k + t + 4]);
                af[mi][3] = __float_as_uint(Ab[(r+8)*36 + k + t + 4]);
            }
            unsigned bf[8][2];
            #pragma unroll
            for (int ni=0;ni<8;ni++){
                int n = wn + ni*8 + g;
                bf[ni][0] = __float_as_uint(Bb[(k+t)*136 + n]);
                bf[ni][1] = __float_as_uint(Bb[(k+t+4)*136 + n]);
            }
            #pragma unroll
            for (int mi=0;mi<2;mi++)
                #pragma unroll
                for (int ni=0;ni<8;ni++)
                    mma8(acc[mi][ni], af[mi], bf[ni]);
        }
    };

    LOADT(0); STORET(0); __syncthreads();
    int buf = 0;
    for (int kt=0; kt<KT; kt++){
        if (kt+1 < KT) LOADT(kt+1);
        COMPUTE(buf);
        if (kt+1 < KT) STORET(buf^1);
        __syncthreads();
        buf ^= 1;
    }

    // epilogue: + cmul(D, x), write directly in (b,t,d,2) layout
    #pragma unroll
    for (int mi=0;mi<2;mi++){
        int row = mt*128 + wm + mi*16 + g;
        #pragma unroll
        for (int ni=0;ni<8;ni++){
            int ncol = nt*128 + wn + ni*8 + t*2;   // even
            int d = ncol >> 1;
            float2 Dv  = *reinterpret_cast<const float2*>(&Dp[d*2]);
            float2 xv0 = *reinterpret_cast<const float2*>(&x[((size_t)row*DIMM + d)*2]);
            float2 xv1 = *reinterpret_cast<const float2*>(&x[((size_t)(row+8)*DIMM + d)*2]);
            float y00 = acc[mi][ni][0] + Dv.x*xv0.x - Dv.y*xv0.y;
            float y01 = acc[mi][ni][1] + Dv.x*xv0.y + Dv.y*xv0.x;
            float y10 = acc[mi][ni][2] + Dv.x*xv1.x - Dv.y*xv1.y;
            float y11 = acc[mi][ni][3] + Dv.x*xv1.y + Dv.y*xv1.x;
            *reinterpret_cast<float2*>(&out[(size_t)row*N2 + ncol])     = make_float2(y00,y01);
            *reinterpret_cast<float2*>(&out[(size_t)(row+8)*N2 + ncol]) = make_float2(y10,y11);
        }
    }
}

// ---------------- launch ----------------
extern "C" void kernel_launch(void* const* d_in, const int* in_sizes, int n_in,
                              void* d_out, int out_size){
    const float* x       = (const float*)d_in[0];
    const float* lAr     = (const float*)d_in[1];
    const float* lAi     = (const float*)d_in[2];
    const float* Dp      = (const float*)d_in[3];
    const float* dt_w    = (const float*)d_in[4];
    const float* dt_b    = (const float*)d_in[5];
    const float* dt_bias = (const float*)d_in[6];
    const float* Br      = (const float*)d_in[7];
    const float* Bi      = (const float*)d_in[8];
    const float* Cr      = (const float*)d_in[9];
    const float* Ci      = (const float*)d_in[10];
    const float* pg_w    = (const float*)d_in[11];
    const float* pg_b    = (const float*)d_in[12];
    float* out = (float*)d_out;

    const size_t shmem = (size_t)(2*ASZ + 2*BSZ) * sizeof(float);   // 71,680 B
    cudaFuncSetAttribute(gemm1, cudaFuncAttributeMaxDynamicSharedMemorySize, (int)shmem);
    cudaFuncSetAttribute(gemm2, cudaFuncAttributeMaxDynamicSharedMemorySize, (int)shmem);

    prep_w1<<<(K1*N1)/256, 256>>>(dt_w, Br, Bi, pg_w);
    prep_w2<<<(K2*N2)/256, 256>>>(Cr, Ci);
    gemm1<<<(MM/128)*4, 256, shmem>>>(x);
    ew1<<<(MM*SS)/256, 256>>>(dt_b, dt_bias, lAr, lAi, pg_b);
    scan_a<<<BB*NC, SS>>>();
    scan_b<<<1, BB*SS>>>();
    scan_c<<<BB*NC, SS>>>(out);
    gemm2<<<(MM/128)*32, 256, shmem>>>(x, Dp, out);
}

// round 7
// speedup vs baseline: 1.0032x; 1.0032x over previous
#include <cuda_runtime.h>
#include <cstdint>
#include <cstddef>

// Problem dims
#define BB   4
#define LL   4096
#define DIMM 2048
#define SS   128
#define MM   (BB*LL)        // 16384 token rows
#define N1   512            // dt | Bx_re | Bx_im | pg
#define K1   6144           // xr(2048) | xi(2048) | cab(2048)
#define K2   256            // hr(128) | hi(128)
#define N2   4096           // interleaved (yr,yi) per d
#define NC   64             // scan chunks per lane
#define CHUNK (LL/NC)       // 64

// smem tile sizes (floats), BLOCK_M=128, BLOCK_N=128, BLOCK_K=32
#define ASZ (128*36)        // A tile [m][k], pad 36 -> conflict free frag loads
#define BSZ (32*136)        // B tile [k][n], pad 136 -> conflict free frag loads

// -------- scratch (no allocations allowed; __device__ globals) --------
__device__ float  g_W1[(size_t)K1*N1];      // packed weights for GEMM1 (tf32-rounded)
__device__ float  g_G1[(size_t)MM*N1];      // GEMM1 raw outputs
__device__ float4 g_ABx[(size_t)MM*SS];     // {Ar,Ai,Bxr,Bxi} per (m,s)
__device__ float2 g_cA[BB*NC*SS];           // chunk A-products
__device__ float2 g_cH[BB*NC*SS];           // chunk local h_end
__device__ float2 g_carry[BB*NC*SS];        // per-chunk carry-in
__device__ float  g_H[(size_t)MM*K2];       // [hr|hi] rows for GEMM2
__device__ float  g_W2[(size_t)K2*N2];      // packed weights for GEMM2 (tf32-rounded)

__device__ __forceinline__ float to_tf32(float v){
    unsigned u; asm("cvt.rna.tf32.f32 %0, %1;" : "=r"(u) : "f"(v));
    return __uint_as_float(u);
}

__device__ __forceinline__ void mma8(float* c, const unsigned* a, const unsigned* b){
    asm volatile(
        "mma.sync.aligned.m16n8k8.row.col.f32.tf32.tf32.f32 "
        "{%0,%1,%2,%3}, {%4,%5,%6,%7}, {%8,%9}, {%0,%1,%2,%3};\n"
        : "+f"(c[0]), "+f"(c[1]), "+f"(c[2]), "+f"(c[3])
        : "r"(a[0]), "r"(a[1]), "r"(a[2]), "r"(a[3]), "r"(b[0]), "r"(b[1]));
}

// ---------------- weight packing ----------------
// W1[k, n], n<128: dt_w; n in [128,256): Bx real; [256,384): Bx imag; [384,512): pg
__global__ void prep_w1(const float* __restrict__ dt_w, const float* __restrict__ Br,
                        const float* __restrict__ Bi,   const float* __restrict__ pg_w){
    int idx = blockIdx.x*256 + threadIdx.x;
    int n = idx & (N1-1);
    int k = idx >> 9;
    float v = 0.f;
    if (n < 128) {
        if (k < 4096) v = dt_w[(size_t)n*4096 + k];
    } else if (n < 256) {
        int s = n - 128;
        if (k < 2048)       v =  Br[(size_t)k*SS + s];
        else if (k < 4096)  v = -Bi[(size_t)(k-2048)*SS + s];
    } else if (n < 384) {
        int s = n - 256;
        if (k < 2048)       v =  Bi[(size_t)k*SS + s];
        else if (k < 4096)  v =  Br[(size_t)(k-2048)*SS + s];
    } else {
        int s = n - 384;
        if (k >= 4096)      v =  pg_w[(size_t)s*DIMM + (k-4096)];
    }
    g_W1[idx] = to_tf32(v);
}

// W2[k, n] with n = 2d+c: k<128 (hr): c? Ci : Cr ; k>=128 (hi): c? Cr : -Ci
__global__ void prep_w2(const float* __restrict__ Cr, const float* __restrict__ Ci){
    int idx = blockIdx.x*256 + threadIdx.x;
    int n = idx & (N2-1);
    int k = idx >> 12;
    int d = n >> 1, c = n & 1;
    float v;
    if (k < 128) v = c ? Ci[(size_t)k*DIMM + d] : Cr[(size_t)k*DIMM + d];
    else { int s = k - 128; v = c ? Cr[(size_t)s*DIMM + d] : -Ci[(size_t)s*DIMM + d]; }
    g_W2[idx] = to_tf32(v);
}

// ---------------- GEMM1: projections ----------------
// grid: blockIdx = mt*4 + nb; nb in {0,1,2}: K range [0,4096) over [xr|xi];
// nb==3: K range [4096,6144) over cab (computed on the fly).
__global__ __launch_bounds__(256,1) void gemm1(const float* __restrict__ x){
    extern __shared__ float smem[];
    float* As = smem;
    float* Bs = smem + 2*ASZ;

    const int tid = threadIdx.x;
    const int nb  = blockIdx.x & 3;
    const int mt  = blockIdx.x >> 2;
    const int kstart = (nb < 3) ? 0 : 4096;
    const int KT     = (nb < 3) ? 128 : 64;

    const int am = tid >> 3;            // A row 0..31 (+32j)
    const int ak = (tid & 7) << 2;      // A k 0..28
    const int bk = tid >> 5;            // B k 0..7 (+8j)
    const int bn = (tid & 31) << 2;     // B n 0..124

    const int lane = tid & 31;
    const int warp = tid >> 5;
    const int wm = (warp >> 1) * 32;    // 4 warps in M
    const int wn = (warp & 1) * 64;     // 2 warps in N
    const int g = lane >> 2;
    const int t = lane & 3;

    float acc[2][8][4];
    #pragma unroll
    for (int mi=0;mi<2;mi++){ 
        #pragma unroll
        for (int ni=0;ni<8;ni++){ acc[mi][ni][0]=0.f; acc[mi][ni][1]=0.f; acc[mi][ni][2]=0.f; acc[mi][ni][3]=0.f; }
    }

    float sa[16], sb[16];

    auto LOADT = [&](int kt){
        const int k0 = kstart + kt*32;
        const int kg = k0 + ak;
        const int d  = (kg < 2048) ? kg : ((kg < 4096) ? kg - 2048 : kg - 4096);
        #pragma unroll
        for (int j=0;j<4;j++){
            int row = mt*128 + am + 32*j;
            const float4* p = reinterpret_cast<const float4*>(x + ((size_t)row*DIMM + d)*2);
            float4 u = p[0], v4 = p[1];
            if (kg < 2048){
                sa[j*4+0]=u.x; sa[j*4+1]=u.z; sa[j*4+2]=v4.x; sa[j*4+3]=v4.z;
            } else if (kg < 4096){
                sa[j*4+0]=u.y; sa[j*4+1]=u.w; sa[j*4+2]=v4.y; sa[j*4+3]=v4.w;
            } else {
                sa[j*4+0]=sqrtf(u.x*u.x+u.y*u.y);
                sa[j*4+1]=sqrtf(u.z*u.z+u.w*u.w);
                sa[j*4+2]=sqrtf(v4.x*v4.x+v4.y*v4.y);
                sa[j*4+3]=sqrtf(v4.z*v4.z+v4.w*v4.w);
            }
        }
        #pragma unroll
        for (int j=0;j<16;j++) sa[j] = to_tf32(sa[j]);
        #pragma unroll
        for (int j=0;j<4;j++){
            int kl = bk + 8*j;
            float4 w = *reinterpret_cast<const float4*>(&g_W1[(size_t)(k0+kl)*N1 + nb*128 + bn]);
            sb[j*4+0]=w.x; sb[j*4+1]=w.y; sb[j*4+2]=w.z; sb[j*4+3]=w.w;
        }
    };
    auto STORET = [&](int buf){
        float* Ab = As + buf*ASZ;
        float* Bb = Bs + buf*BSZ;
        #pragma unroll
        for (int j=0;j<4;j++)
            *reinterpret_cast<float4*>(&Ab[(am+32*j)*36 + ak]) =
                make_float4(sa[j*4],sa[j*4+1],sa[j*4+2],sa[j*4+3]);
        #pragma unroll
        for (int j=0;j<4;j++)
            *reinterpret_cast<float4*>(&Bb[(bk+8*j)*136 + bn]) =
                make_float4(sb[j*4],sb[j*4+1],sb[j*4+2],sb[j*4+3]);
    };
    auto COMPUTE = [&](int buf){
        const float* Ab = As + buf*ASZ;
        const float* Bb = Bs + buf*BSZ;
        #pragma unroll
        for (int kk=0;kk<4;kk++){
            const int k = kk*8;
            unsigned af[2][4];
            #pragma unroll
            for (int mi=0;mi<2;mi++){
                int r = wm + mi*16 + g;
                af[mi][0] = __float_as_uint(Ab[r*36 + k + t]);
                af[mi][1] = __float_as_uint(Ab[(r+8)*36 + k + t]);
                af[mi][2] = __float_as_uint(Ab[r*36 + k + t + 4]);
                af[mi][3] = __float_as_uint(Ab[(r+8)*36 + k + t + 4]);
            }
            unsigned bf[8][2];
            #pragma unroll
            for (int ni=0;ni<8;ni++){
                int n = wn + ni*8 + g;
                bf[ni][0] = __float_as_uint(Bb[(k+t)*136 + n]);
                bf[ni][1] = __float_as_uint(Bb[(k+t+4)*136 + n]);
            }
            #pragma unroll
            for (int mi=0;mi<2;mi++)
                #pragma unroll
                for (int ni=0;ni<8;ni++)
                    mma8(acc[mi][ni], af[mi], bf[ni]);
        }
    };

    LOADT(0); STORET(0); __syncthreads();
    int buf = 0;
    for (int kt=0; kt<KT; kt++){
        if (kt+1 < KT) LOADT(kt+1);
        COMPUTE(buf);
        if (kt+1 < KT) STORET(buf^1);
        __syncthreads();
        buf ^= 1;
    }

    #pragma unroll
    for (int mi=0;mi<2;mi++){
        int row = mt*128 + wm + mi*16 + g;
        #pragma unroll
        for (int ni=0;ni<8;ni++){
            int col = nb*128 + wn + ni*8 + t*2;
            *reinterpret_cast<float2*>(&g_G1[(size_t)row*N1 + col])     = make_float2(acc[mi][ni][0], acc[mi][ni][1]);
            *reinterpret_cast<float2*>(&g_G1[(size_t)(row+8)*N1 + col]) = make_float2(acc[mi][ni][2], acc[mi][ni][3]);
        }
    }
}

// ---------------- elementwise: build A, Bx ----------------
__global__ void ew1(const float* __restrict__ dt_b, const float* __restrict__ dt_bias,
                    const float* __restrict__ lAr,  const float* __restrict__ lAi,
                    const float* __restrict__ pg_b){
    __shared__ float s_ear[SS], s_cos[SS], s_sin[SS], s_db[SS], s_pb[SS];
    int tid = threadIdx.x;
    if (tid < SS){
        s_ear[tid] = expf(lAr[tid]);
        float sn, cs; sincosf(lAi[tid], &sn, &cs);
        s_cos[tid]=cs; s_sin[tid]=sn;
        s_db[tid] = dt_b[tid] + dt_bias[tid];
        s_pb[tid] = pg_b[tid];
    }
    __syncthreads();
    size_t idx = (size_t)blockIdx.x*256 + tid;      // over MM*SS
    int s = (int)(idx & 127);
    size_t m = idx >> 7;
    const float* row = &g_G1[m*N1];
    float z  = row[s] + s_db[s];
    float dt = (z > 20.f) ? z : log1pf(expf(z));
    float bxr = row[128+s], bxi = row[256+s];
    float pz  = row[384+s] + s_pb[s];
    float p   = 1.f/(1.f+expf(-pz));
    float am  = expf(-dt * s_ear[s]);
    float omp = 1.f - p;
    float Ar = p + omp*am*s_cos[s];
    float Ai = omp*am*s_sin[s];
    float sc = omp*dt;
    g_ABx[idx] = make_float4(Ar, Ai, bxr*sc, bxi*sc);
}

// ---------------- chunked scan ----------------
__global__ void scan_a(){
    int b = blockIdx.x >> 6;
    int c = blockIdx.x & (NC-1);
    int s = threadIdx.x;
    size_t base = ((size_t)b*LL + (size_t)c*CHUNK)*SS + s;
    float hr=0.f, hi=0.f, pr=1.f, pi=0.f;
    #pragma unroll 4
    for (int i=0;i<CHUNK;i++){
        float4 v = g_ABx[base + (size_t)i*SS];
        float nhr = v.x*hr - v.y*hi + v.z;
        float nhi = v.x*hi + v.y*hr + v.w;
        float npr = v.x*pr - v.y*pi;
        float npi = v.x*pi + v.y*pr;
        hr=nhr; hi=nhi; pr=npr; pi=npi;
    }
    int o = (b*NC + c)*SS + s;
    g_cA[o] = make_float2(pr,pi);
    g_cH[o] = make_float2(hr,hi);
}

__global__ void scan_b(){
    int tid = threadIdx.x;            // 512 = BB*SS
    int b = tid >> 7, s = tid & 127;
    float cr=0.f, ci=0.f;
    for (int c=0;c<NC;c++){
        int o = (b*NC + c)*SS + s;
        g_carry[o] = make_float2(cr,ci);
        float2 a = g_cA[o]; float2 h = g_cH[o];
        float nr  = a.x*cr - a.y*ci + h.x;
        float ni2 = a.x*ci + a.y*cr + h.y;
        cr=nr; ci=ni2;
    }
}

__global__ void scan_c(float* __restrict__ out){
    int b = blockIdx.x >> 6;
    int c = blockIdx.x & (NC-1);
    int s = threadIdx.x;
    int o = (b*NC + c)*SS + s;
    float2 cc = g_carry[o];
    float hr = cc.x, hi = cc.y;
    size_t base  = ((size_t)b*LL + (size_t)c*CHUNK)*SS + s;
    size_t mbase = (size_t)b*LL + (size_t)c*CHUNK;
    for (int i=0;i<CHUNK;i++){
        float4 v = g_ABx[base + (size_t)i*SS];
        float nhr = v.x*hr - v.y*hi + v.z;
        float nhi = v.x*hi + v.y*hr + v.w;
        hr=nhr; hi=nhi;
        size_t m = mbase + i;
        g_H[m*K2 + s]       = hr;
        g_H[m*K2 + 128 + s] = hi;
    }
    if (c == NC-1){
        out[(size_t)MM*N2 + (b*SS + s)*2 + 0] = hr;
        out[(size_t)MM*N2 + (b*SS + s)*2 + 1] = hi;
    }
}

// ---------------- GEMM2: y = [hr|hi] @ W2 + D*x ----------------
__global__ __launch_bounds__(256,1) void gemm2(const float* __restrict__ x,
                                               const float* __restrict__ Dp,
                                               float* __restrict__ out){
    extern __shared__ float smem[];
    float* As = smem;
    float* Bs = smem + 2*ASZ;

    const int tid = threadIdx.x;
    const int nt  = blockIdx.x & 31;
    const int mt  = blockIdx.x >> 5;
    const int KT  = K2/32;   // 8

    const int am = tid >> 3;
    const int ak = (tid & 7) << 2;
    const int bk = tid >> 5;
    const int bn = (tid & 31) << 2;

    const int lane = tid & 31;
    const int warp = tid >> 5;
    const int wm = (warp >> 1) * 32;
    const int wn = (warp & 1) * 64;
    const int g = lane >> 2;
    const int t = lane & 3;

    float acc[2][8][4];
    #pragma unroll
    for (int mi=0;mi<2;mi++){
        #pragma unroll
        for (int ni=0;ni<8;ni++){ acc[mi][ni][0]=0.f; acc[mi][ni][1]=0.f; acc[mi][ni][2]=0.f; acc[mi][ni][3]=0.f; }
    }

    float sa[16], sb[16];

    auto LOADT = [&](int kt){
        const int k0 = kt*32;
        #pragma unroll
        for (int j=0;j<4;j++){
            int row = mt*128 + am + 32*j;
            float4 h4 = *reinterpret_cast<const float4*>(&g_H[(size_t)row*K2 + k0 + ak]);
            sa[j*4+0]=to_tf32(h4.x); sa[j*4+1]=to_tf32(h4.y);
            sa[j*4+2]=to_tf32(h4.z); sa[j*4+3]=to_tf32(h4.w);
        }
        #pragma unroll
        for (int j=0;j<4;j++){
            int kl = bk + 8*j;
            float4 w = *reinterpret_cast<const float4*>(&g_W2[(size_t)(k0+kl)*N2 + nt*128 + bn]);
            sb[j*4+0]=w.x; sb[j*4+1]=w.y; sb[j*4+2]=w.z; sb[j*4+3]=w.w;
        }
    };
    auto STORET = [&](int buf){
        float* Ab = As + buf*ASZ;
        float* Bb = Bs + buf*BSZ;
        #pragma unroll
        for (int j=0;j<4;j++)
            *reinterpret_cast<float4*>(&Ab[(am+32*j)*36 + ak]) =
                make_float4(sa[j*4],sa[j*4+1],sa[j*4+2],sa[j*4+3]);
        #pragma unroll
        for (int j=0;j<4;j++)
            *reinterpret_cast<float4*>(&Bb[(bk+8*j)*136 + bn]) =
                make_float4(sb[j*4],sb[j*4+1],sb[j*4+2],sb[j*4+3]);
    };
    auto COMPUTE = [&](int buf){
        const float* Ab = As + buf*ASZ;
        const float* Bb = Bs + buf*BSZ;
        #pragma unroll
        for (int kk=0;kk<4;kk++){
            const int k = kk*8;
            unsigned af[2][4];
            #pragma unroll
            for (int mi=0;mi<2;mi++){
                int r = wm + mi*16 + g;
                af[mi][0] = __float_as_uint(Ab[r*36 + k + t]);
                af[mi][1] = __float_as_uint(Ab[(r+8)*36 + k + t]);
                af[mi][2] = __float_as_uint(Ab[r*36 + k + t + 4]);
                af[mi][3] = __float_as_uint(Ab[(r+8)*36 + k + t + 4]);
            }
            unsigned bf[8][2];
            #pragma unroll
            for (int ni=0;ni<8;ni++){
                int n = wn + ni*8 + g;
                bf[ni][0] = __float_as_uint(Bb[(k+t)*136 + n]);
                bf[ni][1] = __float_as_uint(Bb[(k+t+4)*136 + n]);
            }
            #pragma unroll
            for (int mi=0;mi<2;mi++)
                #pragma unroll
                for (int ni=0;ni<8;ni++)
                    mma8(acc[mi][ni], af[mi], bf[ni]);
        }
    };

    LOADT(0); STORET(0); __syncthreads();
    int buf = 0;
    for (int kt=0; kt<KT; kt++){
        if (kt+1 < KT) LOADT(kt+1);
        COMPUTE(buf);
        if (kt+1 < KT) STORET(buf^1);
        __syncthreads();
        buf ^= 1;
    }

    // epilogue: + cmul(D, x), write directly in (b,t,d,2) layout
    #pragma unroll
    for (int mi=0;mi<2;mi++){
        int row = mt*128 + wm + mi*16 + g;
        #pragma unroll
        for (int ni=0;ni<8;ni++){
            int ncol = nt*128 + wn + ni*8 + t*2;   // even
            int d = ncol >> 1;
            float2 Dv  = *reinterpret_cast<const float2*>(&Dp[d*2]);
            float2 xv0 = *reinterpret_cast<const float2*>(&x[((size_t)row*DIMM + d)*2]);
            float2 xv1 = *reinterpret_cast<const float2*>(&x[((size_t)(row+8)*DIMM + d)*2]);
            float y00 = acc[mi][ni][0] + Dv.x*xv0.x - Dv.y*xv0.y;
            float y01 = acc[mi][ni][1] + Dv.x*xv0.y + Dv.y*xv0.x;
            float y10 = acc[mi][ni][2] + Dv.x*xv1.x - Dv.y*xv1.y;
            float y11 = acc[mi][ni][3] + Dv.x*xv1.y + Dv.y*xv1.x;
            *reinterpret_cast<float2*>(&out[(size_t)row*N2 + ncol])     = make_float2(y00,y01);
            *reinterpret_cast<float2*>(&out[(size_t)(row+8)*N2 + ncol]) = make_float2(y10,y11);
        }
    }
}

// ---------------- launch ----------------
extern "C" void kernel_launch(void* const* d_in, const int* in_sizes, int n_in,
                              void* d_out, int out_size){
    const float* x       = (const float*)d_in[0];
    const float* lAr     = (const float*)d_in[1];
    const float* lAi     = (const float*)d_in[2];
    const float* Dp      = (const float*)d_in[3];
    const float* dt_w    = (const float*)d_in[4];
    const float* dt_b    = (const float*)d_in[5];
    const float* dt_bias = (const float*)d_in[6];
    const float* Br      = (const float*)d_in[7];
    const float* Bi      = (const float*)d_in[8];
    const float* Cr      = (const float*)d_in[9];
    const float* Ci      = (const float*)d_in[10];
    const float* pg_w    = (const float*)d_in[11];
    const float* pg_b    = (const float*)d_in[12];
    float* out = (float*)d_out;

    const size_t shmem = (size_t)(2*ASZ + 2*BSZ) * sizeof(float);   // 71,680 B
    cudaFuncSetAttribute(gemm1, cudaFuncAttributeMaxDynamicSharedMemorySize, (int)shmem);
    cudaFuncSetAttribute(gemm2, cudaFuncAttributeMaxDynamicSharedMemorySize, (int)shmem);

    prep_w1<<<(K1*N1)/256, 256>>>(dt_w, Br, Bi, pg_w);
    prep_w2<<<(K2*N2)/256, 256>>>(Cr, Ci);
    gemm1<<<(MM/128)*4, 256, shmem>>>(x);
    ew1<<<(MM*SS)/256, 256>>>(dt_b, dt_bias, lAr, lAi, pg_b);
    scan_a<<<BB*NC, SS>>>();
    scan_b<<<1, BB*SS>>>();
    scan_c<<<BB*NC, SS>>>(out);
    gemm2<<<(MM/128)*32, 256, shmem>>>(x, Dp, out);
}

// round 12
// speedup vs baseline: 1.3146x; 1.3104x over previous
#include <cuda_runtime.h>
#include <cuda_fp16.h>
#include <cstdint>
#include <cstddef>

// Problem dims
#define BB   4
#define LL   4096
#define DIMM 2048
#define SS   128
#define MM   (BB*LL)        // 16384 token rows
#define N1   512            // dt | Bx_re | Bx_im | pg
#define K1   6144           // xr(2048) | xi(2048) | cab(2048)
#define K2   256            // hr(128) | hi(128)
#define N2   4096           // interleaved (yr,yi) per d
#define NC   64             // scan chunks per lane
#define CHUNK (LL/NC)       // 64

// SMEM tiles: 128 rows x 32 k halves, padded to 40 halves/row (80B = 20 banks,
// (20g+t) mod 32 covers all banks -> conflict-free fragment loads)
#define TPAD 40
#define TSZ  (128*TPAD)

// -------- scratch (__device__ globals; no allocations allowed) --------
__device__ __half g_W1h[(size_t)N1*K1];     // GEMM1 B operand, [n][k], fp16
__device__ __half g_W2h[(size_t)N2*K2];     // GEMM2 B operand, [n][k], fp16
__device__ float  g_G1[(size_t)MM*N1];      // GEMM1 fp32 outputs
__device__ float4 g_ABx[(size_t)MM*SS];     // {Ar,Ai,Bxr,Bxi} per (m,s)
__device__ float2 g_cA[BB*NC*SS];           // chunk A-products
__device__ float2 g_cH[BB*NC*SS];           // chunk local h_end
__device__ float2 g_carry[BB*NC*SS];        // per-chunk carry-in
__device__ __half g_Hh[(size_t)MM*K2];      // [hr|hi] rows, fp16, for GEMM2

__device__ __forceinline__ void mma16(float* c, const unsigned* a, const unsigned* b){
    asm volatile(
        "mma.sync.aligned.m16n8k16.row.col.f32.f16.f16.f32 "
        "{%0,%1,%2,%3}, {%4,%5,%6,%7}, {%8,%9}, {%0,%1,%2,%3};\n"
        : "+f"(c[0]), "+f"(c[1]), "+f"(c[2]), "+f"(c[3])
        : "r"(a[0]), "r"(a[1]), "r"(a[2]), "r"(a[3]), "r"(b[0]), "r"(b[1]));
}

// ---------------- weight packing ([n][k] fp16) ----------------
__global__ void prep_w1h(const float* __restrict__ dt_w, const float* __restrict__ Br,
                         const float* __restrict__ Bi,   const float* __restrict__ pg_w){
    size_t idx = (size_t)blockIdx.x*256 + threadIdx.x;   // over N1*K1, k fast
    int n = (int)(idx / K1);
    int k = (int)(idx - (size_t)n*K1);
    float v = 0.f;
    if (n < 128) {
        if (k < 4096) v = dt_w[(size_t)n*4096 + k];
    } else if (n < 256) {
        int s = n - 128;
        if (k < 2048)       v =  Br[(size_t)k*SS + s];
        else if (k < 4096)  v = -Bi[(size_t)(k-2048)*SS + s];
    } else if (n < 384) {
        int s = n - 256;
        if (k < 2048)       v =  Bi[(size_t)k*SS + s];
        else if (k < 4096)  v =  Br[(size_t)(k-2048)*SS + s];
    } else {
        int s = n - 384;
        if (k >= 4096)      v =  pg_w[(size_t)s*DIMM + (k-4096)];
    }
    g_W1h[idx] = __float2half_rn(v);
}

// W2: n = 2d+c; k<128 (hr): c? Ci : Cr ; k>=128 (hi): c? Cr : -Ci
__global__ void prep_w2h(const float* __restrict__ Cr, const float* __restrict__ Ci){
    size_t idx = (size_t)blockIdx.x*256 + threadIdx.x;   // over N2*K2, k fast
    int n = (int)(idx >> 8);
    int k = (int)(idx & 255);
    int d = n >> 1, c = n & 1;
    float v;
    if (k < 128) v = c ? Ci[(size_t)k*DIMM + d] : Cr[(size_t)k*DIMM + d];
    else { int s = k - 128; v = c ? Cr[(size_t)s*DIMM + d] : -Ci[(size_t)s*DIMM + d]; }
    g_W2h[idx] = __float2half_rn(v);
}

// ---------------- GEMM1: projections (fp16 HMMA) ----------------
// grid: blockIdx = mt*4 + nb; nb 0..2: K in [0,4096) over [xr|xi]; nb==3: cab K=2048.
__global__ __launch_bounds__(256,1) void gemm1(const float* __restrict__ x){
    __shared__ __half As[2][TSZ];
    __shared__ __half Bs[2][TSZ];

    const int tid = threadIdx.x;
    const int nb  = blockIdx.x & 3;
    const int mt  = blockIdx.x >> 2;
    const int kstart = (nb < 3) ? 0 : 4096;
    const int KT     = (nb < 3) ? 128 : 64;

    const int lrow = tid >> 1;           // 0..127 (A row / B n-row)
    const int kc   = (tid & 1) * 16;     // k sub-offset

    const int lane = tid & 31;
    const int warp = tid >> 5;
    const int wm = (warp >> 1) * 32;     // 4 warps in M
    const int wn = (warp & 1) * 64;      // 2 warps in N
    const int g = lane >> 2;
    const int t = lane & 3;

    float acc[2][8][4];
    #pragma unroll
    for (int mi=0;mi<2;mi++)
        #pragma unroll
        for (int ni=0;ni<8;ni++){ acc[mi][ni][0]=0.f; acc[mi][ni][1]=0.f; acc[mi][ni][2]=0.f; acc[mi][ni][3]=0.f; }

    uint4 ra[2], rb[2];
    const float4* xr4 = reinterpret_cast<const float4*>(x) + ((size_t)(mt*128 + lrow)*DIMM)/2;
    const __half* wrow = g_W1h + (size_t)(nb*128 + lrow)*K1;

    auto LOADT = [&](int kt){
        const int k0 = kstart + kt*32;
        // ---- A: 16 halves from x ----
        const int comp = (k0 - kstart >= 2048 && nb < 3) ? 1 : 0; // nb<3: xr then xi
        const int d0 = (nb < 3) ? (k0 - (comp ? 2048 : 0) + kc) : (k0 - 4096 + kc);
        const float4* p = xr4 + (d0 >> 1);   // each float4 = two (re,im) pairs
        __half2 hh[8];
        #pragma unroll
        for (int i=0;i<8;i++){
            float4 v = p[i];
            float f0, f1;
            if (nb == 3){ f0 = sqrtf(v.x*v.x + v.y*v.y); f1 = sqrtf(v.z*v.z + v.w*v.w); }
            else if (comp){ f0 = v.y; f1 = v.w; }
            else          { f0 = v.x; f1 = v.z; }
            hh[i] = __floats2half2_rn(f0, f1);
        }
        ra[0] = *reinterpret_cast<uint4*>(&hh[0]);
        ra[1] = *reinterpret_cast<uint4*>(&hh[4]);
        // ---- B: 16 halves from packed weights ----
        const uint4* ws = reinterpret_cast<const uint4*>(wrow + k0 + kc);
        rb[0] = ws[0]; rb[1] = ws[1];
    };
    auto STORET = [&](int buf){
        *reinterpret_cast<uint4*>(&As[buf][lrow*TPAD + kc])     = ra[0];
        *reinterpret_cast<uint4*>(&As[buf][lrow*TPAD + kc + 8]) = ra[1];
        *reinterpret_cast<uint4*>(&Bs[buf][lrow*TPAD + kc])     = rb[0];
        *reinterpret_cast<uint4*>(&Bs[buf][lrow*TPAD + kc + 8]) = rb[1];
    };
    auto COMPUTE = [&](int buf){
        const __half* Ab = As[buf];
        const __half* Bb = Bs[buf];
        #pragma unroll
        for (int ks=0; ks<2; ks++){
            const int kb = ks*16;
            unsigned a[2][4];
            #pragma unroll
            for (int mi=0;mi<2;mi++){
                int r = wm + mi*16 + g;
                a[mi][0] = *reinterpret_cast<const unsigned*>(&Ab[r*TPAD + kb + t*2]);
                a[mi][1] = *reinterpret_cast<const unsigned*>(&Ab[(r+8)*TPAD + kb + t*2]);
                a[mi][2] = *reinterpret_cast<const unsigned*>(&Ab[r*TPAD + kb + t*2 + 8]);
                a[mi][3] = *reinterpret_cast<const unsigned*>(&Ab[(r+8)*TPAD + kb + t*2 + 8]);
            }
            unsigned b[8][2];
            #pragma unroll
            for (int ni=0;ni<8;ni++){
                int n = wn + ni*8 + g;
                b[ni][0] = *reinterpret_cast<const unsigned*>(&Bb[n*TPAD + kb + t*2]);
                b[ni][1] = *reinterpret_cast<const unsigned*>(&Bb[n*TPAD + kb + t*2 + 8]);
            }
            #pragma unroll
            for (int mi=0;mi<2;mi++)
                #pragma unroll
                for (int ni=0;ni<8;ni++)
                    mma16(acc[mi][ni], a[mi], b[ni]);
        }
    };

    LOADT(0); STORET(0); __syncthreads();
    int buf = 0;
    for (int kt=0; kt<KT; kt++){
        if (kt+1 < KT) LOADT(kt+1);
        COMPUTE(buf);
        if (kt+1 < KT) STORET(buf^1);
        __syncthreads();
        buf ^= 1;
    }

    #pragma unroll
    for (int mi=0;mi<2;mi++){
        int row = mt*128 + wm + mi*16 + g;
        #pragma unroll
        for (int ni=0;ni<8;ni++){
            int col = nb*128 + wn + ni*8 + t*2;
            *reinterpret_cast<float2*>(&g_G1[(size_t)row*N1 + col])     = make_float2(acc[mi][ni][0], acc[mi][ni][1]);
            *reinterpret_cast<float2*>(&g_G1[(size_t)(row+8)*N1 + col]) = make_float2(acc[mi][ni][2], acc[mi][ni][3]);
        }
    }
}

// ---------------- elementwise: build A, Bx ----------------
__global__ void ew1(const float* __restrict__ dt_b, const float* __restrict__ dt_bias,
                    const float* __restrict__ lAr,  const float* __restrict__ lAi,
                    const float* __restrict__ pg_b){
    __shared__ float s_ear[SS], s_cos[SS], s_sin[SS], s_db[SS], s_pb[SS];
    int tid = threadIdx.x;
    if (tid < SS){
        s_ear[tid] = expf(lAr[tid]);
        float sn, cs; sincosf(lAi[tid], &sn, &cs);
        s_cos[tid]=cs; s_sin[tid]=sn;
        s_db[tid] = dt_b[tid] + dt_bias[tid];
        s_pb[tid] = pg_b[tid];
    }
    __syncthreads();
    size_t idx = (size_t)blockIdx.x*256 + tid;      // over MM*SS
    int s = (int)(idx & 127);
    size_t m = idx >> 7;
    const float* row = &g_G1[m*N1];
    float z  = row[s] + s_db[s];
    float dt = (z > 20.f) ? z : log1pf(expf(z));
    float bxr = row[128+s], bxi = row[256+s];
    float pz  = row[384+s] + s_pb[s];
    float p   = 1.f/(1.f+expf(-pz));
    float am  = expf(-dt * s_ear[s]);
    float omp = 1.f - p;
    float Ar = p + omp*am*s_cos[s];
    float Ai = omp*am*s_sin[s];
    float sc = omp*dt;
    g_ABx[idx] = make_float4(Ar, Ai, bxr*sc, bxi*sc);
}

// ---------------- chunked scan ----------------
__global__ void scan_a(){
    int b = blockIdx.x >> 6;
    int c = blockIdx.x & (NC-1);
    int s = threadIdx.x;
    size_t base = ((size_t)b*LL + (size_t)c*CHUNK)*SS + s;
    float hr=0.f, hi=0.f, pr=1.f, pi=0.f;
    #pragma unroll 4
    for (int i=0;i<CHUNK;i++){
        float4 v = g_ABx[base + (size_t)i*SS];
        float nhr = v.x*hr - v.y*hi + v.z;
        float nhi = v.x*hi + v.y*hr + v.w;
        float npr = v.x*pr - v.y*pi;
        float npi = v.x*pi + v.y*pr;
        hr=nhr; hi=nhi; pr=npr; pi=npi;
    }
    int o = (b*NC + c)*SS + s;
    g_cA[o] = make_float2(pr,pi);
    g_cH[o] = make_float2(hr,hi);
}

__global__ void scan_b(){
    int tid = threadIdx.x;            // 512 = BB*SS
    int b = tid >> 7, s = tid & 127;
    float cr=0.f, ci=0.f;
    for (int c=0;c<NC;c++){
        int o = (b*NC + c)*SS + s;
        g_carry[o] = make_float2(cr,ci);
        float2 a = g_cA[o]; float2 h = g_cH[o];
        float nr  = a.x*cr - a.y*ci + h.x;
        float ni2 = a.x*ci + a.y*cr + h.y;
        cr=nr; ci=ni2;
    }
}

__global__ void scan_c(float* __restrict__ out){
    int b = blockIdx.x >> 6;
    int c = blockIdx.x & (NC-1);
    int s = threadIdx.x;
    int o = (b*NC + c)*SS + s;
    float2 cc = g_carry[o];
    float hr = cc.x, hi = cc.y;
    size_t base  = ((size_t)b*LL + (size_t)c*CHUNK)*SS + s;
    size_t mbase = (size_t)b*LL + (size_t)c*CHUNK;
    for (int i=0;i<CHUNK;i++){
        float4 v = g_ABx[base + (size_t)i*SS];
        float nhr = v.x*hr - v.y*hi + v.z;
        float nhi = v.x*hi + v.y*hr + v.w;
        hr=nhr; hi=nhi;
        size_t m = mbase + i;
        g_Hh[m*K2 + s]       = __float2half_rn(hr);
        g_Hh[m*K2 + 128 + s] = __float2half_rn(hi);
    }
    if (c == NC-1){
        out[(size_t)MM*N2 + (b*SS + s)*2 + 0] = hr;
        out[(size_t)MM*N2 + (b*SS + s)*2 + 1] = hi;
    }
}

// ---------------- GEMM2: y = [hr|hi] @ W2 + cmul(D,x) ----------------
__global__ __launch_bounds__(256,1) void gemm2(const float* __restrict__ x,
                                               const float* __restrict__ Dp,
                                               float* __restrict__ out){
    __shared__ __half As[2][TSZ];
    __shared__ __half Bs[2][TSZ];

    const int tid = threadIdx.x;
    const int nt  = blockIdx.x & 31;
    const int mt  = blockIdx.x >> 5;
    const int KT  = K2/32;   // 8

    const int lrow = tid >> 1;
    const int kc   = (tid & 1) * 16;

    const int lane = tid & 31;
    const int warp = tid >> 5;
    const int wm = (warp >> 1) * 32;
    const int wn = (warp & 1) * 64;
    const int g = lane >> 2;
    const int t = lane & 3;

    float acc[2][8][4];
    #pragma unroll
    for (int mi=0;mi<2;mi++)
        #pragma unroll
        for (int ni=0;ni<8;ni++){ acc[mi][ni][0]=0.f; acc[mi][ni][1]=0.f; acc[mi][ni][2]=0.f; acc[mi][ni][3]=0.f; }

    uint4 ra[2], rb[2];
    const __half* hrow = g_Hh + (size_t)(mt*128 + lrow)*K2;
    const __half* wrow = g_W2h + (size_t)(nt*128 + lrow)*K2;

    auto LOADT = [&](int kt){
        const int k0 = kt*32;
        const uint4* hs = reinterpret_cast<const uint4*>(hrow + k0 + kc);
        ra[0] = hs[0]; ra[1] = hs[1];
        const uint4* ws = reinterpret_cast<const uint4*>(wrow + k0 + kc);
        rb[0] = ws[0]; rb[1] = ws[1];
    };
    auto STORET = [&](int buf){
        *reinterpret_cast<uint4*>(&As[buf][lrow*TPAD + kc])     = ra[0];
        *reinterpret_cast<uint4*>(&As[buf][lrow*TPAD + kc + 8]) = ra[1];
        *reinterpret_cast<uint4*>(&Bs[buf][lrow*TPAD + kc])     = rb[0];
        *reinterpret_cast<uint4*>(&Bs[buf][lrow*TPAD + kc + 8]) = rb[1];
    };
    auto COMPUTE = [&](int buf){
        const __half* Ab = As[buf];
        const __half* Bb = Bs[buf];
        #pragma unroll
        for (int ks=0; ks<2; ks++){
            const int kb = ks*16;
            unsigned a[2][4];
            #pragma unroll
            for (int mi=0;mi<2;mi++){
                int r = wm + mi*16 + g;
                a[mi][0] = *reinterpret_cast<const unsigned*>(&Ab[r*TPAD + kb + t*2]);
                a[mi][1] = *reinterpret_cast<const unsigned*>(&Ab[(r+8)*TPAD + kb + t*2]);
                a[mi][2] = *reinterpret_cast<const unsigned*>(&Ab[r*TPAD + kb + t*2 + 8]);
                a[mi][3] = *reinterpret_cast<const unsigned*>(&Ab[(r+8)*TPAD + kb + t*2 + 8]);
            }
            unsigned b[8][2];
            #pragma unroll
            for (int ni=0;ni<8;ni++){
                int n = wn + ni*8 + g;
                b[ni][0] = *reinterpret_cast<const unsigned*>(&Bb[n*TPAD + kb + t*2]);
                b[ni][1] = *reinterpret_cast<const unsigned*>(&Bb[n*TPAD + kb + t*2 + 8]);
            }
            #pragma unroll
            for (int mi=0;mi<2;mi++)
                #pragma unroll
                for (int ni=0;ni<8;ni++)
                    mma16(acc[mi][ni], a[mi], b[ni]);
        }
    };

    LOADT(0); STORET(0); __syncthreads();
    int buf = 0;
    for (int kt=0; kt<KT; kt++){
        if (kt+1 < KT) LOADT(kt+1);
        COMPUTE(buf);
        if (kt+1 < KT) STORET(buf^1);
        __syncthreads();
        buf ^= 1;
    }

    // epilogue: + cmul(D, x), write directly in (b,t,d,2) layout
    #pragma unroll
    for (int mi=0;mi<2;mi++){
        int row = mt*128 + wm + mi*16 + g;
        #pragma unroll
        for (int ni=0;ni<8;ni++){
            int ncol = nt*128 + wn + ni*8 + t*2;   // even
            int d = ncol >> 1;
            float2 Dv  = *reinterpret_cast<const float2*>(&Dp[d*2]);
            float2 xv0 = *reinterpret_cast<const float2*>(&x[((size_t)row*DIMM + d)*2]);
            float2 xv1 = *reinterpret_cast<const float2*>(&x[((size_t)(row+8)*DIMM + d)*2]);
            float y00 = acc[mi][ni][0] + Dv.x*xv0.x - Dv.y*xv0.y;
            float y01 = acc[mi][ni][1] + Dv.x*xv0.y + Dv.y*xv0.x;
            float y10 = acc[mi][ni][2] + Dv.x*xv1.x - Dv.y*xv1.y;
            float y11 = acc[mi][ni][3] + Dv.x*xv1.y + Dv.y*xv1.x;
            *reinterpret_cast<float2*>(&out[(size_t)row*N2 + ncol])     = make_float2(y00,y01);
            *reinterpret_cast<float2*>(&out[(size_t)(row+8)*N2 + ncol]) = make_float2(y10,y11);
        }
    }
}

// ---------------- launch ----------------
extern "C" void kernel_launch(void* const* d_in, const int* in_sizes, int n_in,
                              void* d_out, int out_size){
    const float* x       = (const float*)d_in[0];
    const float* lAr     = (const float*)d_in[1];
    const float* lAi     = (const float*)d_in[2];
    const float* Dp      = (const float*)d_in[3];
    const float* dt_w    = (const float*)d_in[4];
    const float* dt_b    = (const float*)d_in[5];
    const float* dt_bias = (const float*)d_in[6];
    const float* Br      = (const float*)d_in[7];
    const float* Bi      = (const float*)d_in[8];
    const float* Cr      = (const float*)d_in[9];
    const float* Ci      = (const float*)d_in[10];
    const float* pg_w    = (const float*)d_in[11];
    const float* pg_b    = (const float*)d_in[12];
    float* out = (float*)d_out;

    prep_w1h<<<(int)(((size_t)N1*K1)/256), 256>>>(dt_w, Br, Bi, pg_w);
    prep_w2h<<<(int)(((size_t)N2*K2)/256), 256>>>(Cr, Ci);
    gemm1<<<(MM/128)*4, 256>>>(x);
    ew1<<<(MM*SS)/256, 256>>>(dt_b, dt_bias, lAr, lAi, pg_b);
    scan_a<<<BB*NC, SS>>>();
    scan_b<<<1, BB*SS>>>();
    scan_c<<<BB*NC, SS>>>(out);
    gemm2<<<(MM/128)*32, 256>>>(x, Dp, out);
}

// round 13
// speedup vs baseline: 2.4468x; 1.8612x over previous
#include <cuda_runtime.h>
#include <cuda_fp16.h>
#include <cstdint>
#include <cstddef>

// Problem dims
#define BB   4
#define LL   4096
#define DIMM 2048
#define SS   128
#define MM   (BB*LL)        // 16384 token rows
#define N1   512            // dt | Bx_re | Bx_im | pg
#define K1   6144           // xr(2048) | xi(2048) | cab(2048)
#define K2   256            // hr(128) | hi(128)
#define N2   4096           // interleaved (yr,yi) per d
#define NC   64             // scan chunks per lane
#define CHUNK (LL/NC)       // 64

// SMEM tiles: 128 rows x 32 k halves, padded to 40 halves/row (80 B = 20 banks;
// (20r + t) mod 32 covers all banks -> conflict-free ldmatrix phases)
#define TPAD 40
#define TSZ  (128*TPAD)     // halves per tile buffer

// -------- scratch (__device__ globals; no allocations allowed) --------
__device__ __half g_Ah[(size_t)MM*K1];      // fp16 A operand: [xr|xi|cab] per row
__device__ __half g_W1h[(size_t)N1*K1];     // GEMM1 B operand, [n][k], fp16
__device__ __half g_W2h[(size_t)N2*K2];     // GEMM2 B operand, [n][k], fp16
__device__ float  g_G1[(size_t)MM*N1];      // GEMM1 fp32 outputs
__device__ float4 g_ABx[(size_t)MM*SS];     // {Ar,Ai,Bxr,Bxi} per (m,s)
__device__ float2 g_cA[BB*NC*SS];           // chunk A-products
__device__ float2 g_cH[BB*NC*SS];           // chunk local h_end
__device__ float2 g_carry[BB*NC*SS];        // per-chunk carry-in
__device__ __half g_Hh[(size_t)MM*K2];      // [hr|hi] rows, fp16, for GEMM2

__device__ __forceinline__ void mma16(float* c, const unsigned* a, const unsigned* b){
    asm volatile(
        "mma.sync.aligned.m16n8k16.row.col.f32.f16.f16.f32 "
        "{%0,%1,%2,%3}, {%4,%5,%6,%7}, {%8,%9}, {%0,%1,%2,%3};\n"
        : "+f"(c[0]), "+f"(c[1]), "+f"(c[2]), "+f"(c[3])
        : "r"(a[0]), "r"(a[1]), "r"(a[2]), "r"(a[3]), "r"(b[0]), "r"(b[1]));
}
__device__ __forceinline__ void ldsm4(unsigned& r0, unsigned& r1, unsigned& r2, unsigned& r3,
                                      uint32_t addr){
    asm volatile("ldmatrix.sync.aligned.m8n8.x4.shared.b16 {%0,%1,%2,%3}, [%4];"
        : "=r"(r0), "=r"(r1), "=r"(r2), "=r"(r3) : "r"(addr));
}
__device__ __forceinline__ uint32_t smem_u32(const void* p){
    uint32_t a;
    asm("{ .reg .u64 t; cvta.to.shared.u64 t, %1; cvt.u32.u64 %0, t; }" : "=r"(a) : "l"(p));
    return a;
}
#define CP16(dst, src) \
    asm volatile("cp.async.cg.shared.global [%0], [%1], 16;" :: "r"(dst), "l"(src))
#define CPCOMMIT() asm volatile("cp.async.commit_group;" ::: "memory")
#define CPWAIT0()  asm volatile("cp.async.wait_group 0;" ::: "memory")

// ---------------- prep: fp16 A operand [xr | xi | cab] ----------------
__global__ void prep_ah(const float* __restrict__ x){
    size_t idx = (size_t)blockIdx.x*256 + threadIdx.x;   // over MM*DIMM
    size_t m = idx >> 11;
    int d = (int)(idx & 2047);
    float2 v = reinterpret_cast<const float2*>(x)[idx];
    __half* row = g_Ah + m*K1;
    row[d]        = __float2half_rn(v.x);
    row[2048 + d] = __float2half_rn(v.y);
    row[4096 + d] = __float2half_rn(sqrtf(v.x*v.x + v.y*v.y));
}

// ---------------- weight packing ([n][k] fp16) ----------------
__global__ void prep_w1h(const float* __restrict__ dt_w, const float* __restrict__ Br,
                         const float* __restrict__ Bi,   const float* __restrict__ pg_w){
    size_t idx = (size_t)blockIdx.x*256 + threadIdx.x;   // over N1*K1, k fast
    int n = (int)(idx / K1);
    int k = (int)(idx - (size_t)n*K1);
    float v = 0.f;
    if (n < 128) {
        if (k < 4096) v = dt_w[(size_t)n*4096 + k];
    } else if (n < 256) {
        int s = n - 128;
        if (k < 2048)       v =  Br[(size_t)k*SS + s];
        else if (k < 4096)  v = -Bi[(size_t)(k-2048)*SS + s];
    } else if (n < 384) {
        int s = n - 256;
        if (k < 2048)       v =  Bi[(size_t)k*SS + s];
        else if (k < 4096)  v =  Br[(size_t)(k-2048)*SS + s];
    } else {
        int s = n - 384;
        if (k >= 4096)      v =  pg_w[(size_t)s*DIMM + (k-4096)];
    }
    g_W1h[idx] = __float2half_rn(v);
}

__global__ void prep_w2h(const float* __restrict__ Cr, const float* __restrict__ Ci){
    size_t idx = (size_t)blockIdx.x*256 + threadIdx.x;   // over N2*K2, k fast
    int n = (int)(idx >> 8);
    int k = (int)(idx & 255);
    int d = n >> 1, c = n & 1;
    float v;
    if (k < 128) v = c ? Ci[(size_t)k*DIMM + d] : Cr[(size_t)k*DIMM + d];
    else { int s = k - 128; v = c ? Cr[(size_t)s*DIMM + d] : -Ci[(size_t)s*DIMM + d]; }
    g_W2h[idx] = __float2half_rn(v);
}

// ---------------- GEMM1: projections (cp.async + ldmatrix + HMMA) ----------------
// grid: blockIdx = mt*4 + nb; nb 0..2: K=[0,4096); nb==3: K=[4096,6144). 128 thr, 4 warps 64x64.
__global__ __launch_bounds__(128,2) void gemm1(){
    __shared__ __half As[2][TSZ];
    __shared__ __half Bs[2][TSZ];
    const int tid = threadIdx.x, lane = tid & 31, warp = tid >> 5;
    const int nb = blockIdx.x & 3, mt = blockIdx.x >> 2;
    const int kstart = (nb < 3) ? 0 : 4096;
    const int KT     = (nb < 3) ? 128 : 64;
    const int wm = (warp >> 1) * 64, wn = (warp & 1) * 64;

    const __half* Ag = g_Ah  + (size_t)(mt*128 + tid)*K1 + kstart;
    const __half* Bg = g_W1h + (size_t)(nb*128 + tid)*K1 + kstart;
    const uint32_t sA = smem_u32(As), sB = smem_u32(Bs);
    const uint32_t dA = sA + tid*80, dB = sB + tid*80;

    const int arow = (lane & 7) + ((lane >> 3) & 1) * 8;
    const int acol = (lane >> 4) * 8;
    const int brow = (lane & 7) + (lane >> 4) * 8;
    const int bcol = ((lane >> 3) & 1) * 8;
    const uint32_t aoff = sA + ((wm + arow)*TPAD + acol)*2;
    const uint32_t boff = sB + ((wn + brow)*TPAD + bcol)*2;

    float acc[4][8][4];
    #pragma unroll
    for (int mi=0;mi<4;mi++)
        #pragma unroll
        for (int ni=0;ni<8;ni++){ acc[mi][ni][0]=0.f; acc[mi][ni][1]=0.f; acc[mi][ni][2]=0.f; acc[mi][ni][3]=0.f; }

    auto ISSUE = [&](int kt, int buf){
        const __half* a = Ag + kt*32;
        const __half* b = Bg + kt*32;
        uint32_t da = dA + buf*(TSZ*2), db = dB + buf*(TSZ*2);
        #pragma unroll
        for (int s=0;s<4;s++){
            CP16(da + s*16, a + s*8);
            CP16(db + s*16, b + s*8);
        }
        CPCOMMIT();
    };
    auto COMPUTE = [&](int buf){
        const uint32_t ab = aoff + buf*(TSZ*2);
        const uint32_t bb = boff + buf*(TSZ*2);
        #pragma unroll
        for (int ks=0; ks<2; ks++){
            const uint32_t kb2 = ks*32;   // 16 halves * 2B
            unsigned af[4][4], bf[4][4];
            #pragma unroll
            for (int mi=0;mi<4;mi++)
                ldsm4(af[mi][0],af[mi][1],af[mi][2],af[mi][3], ab + mi*16*TPAD*2 + kb2);
            #pragma unroll
            for (int np=0;np<4;np++)
                ldsm4(bf[np][0],bf[np][1],bf[np][2],bf[np][3], bb + np*16*TPAD*2 + kb2);
            #pragma unroll
            for (int mi=0;mi<4;mi++)
                #pragma unroll
                for (int ni=0;ni<8;ni++){
                    unsigned bx[2] = { bf[ni>>1][(ni&1)*2], bf[ni>>1][(ni&1)*2+1] };
                    mma16(acc[mi][ni], af[mi], bx);
                }
        }
    };

    ISSUE(0, 0);
    int buf = 0;
    for (int kt=0; kt<KT; kt++){
        CPWAIT0();
        __syncthreads();
        if (kt+1 < KT) ISSUE(kt+1, buf^1);
        COMPUTE(buf);
        buf ^= 1;
    }

    const int g = lane >> 2, t = lane & 3;
    #pragma unroll
    for (int mi=0;mi<4;mi++){
        int row = mt*128 + wm + mi*16 + g;
        #pragma unroll
        for (int ni=0;ni<8;ni++){
            int col = nb*128 + wn + ni*8 + t*2;
            *reinterpret_cast<float2*>(&g_G1[(size_t)row*N1 + col])     = make_float2(acc[mi][ni][0], acc[mi][ni][1]);
            *reinterpret_cast<float2*>(&g_G1[(size_t)(row+8)*N1 + col]) = make_float2(acc[mi][ni][2], acc[mi][ni][3]);
        }
    }
}

// ---------------- elementwise: build A, Bx ----------------
__global__ void ew1(const float* __restrict__ dt_b, const float* __restrict__ dt_bias,
                    const float* __restrict__ lAr,  const float* __restrict__ lAi,
                    const float* __restrict__ pg_b){
    __shared__ float s_ear[SS], s_cos[SS], s_sin[SS], s_db[SS], s_pb[SS];
    int tid = threadIdx.x;
    if (tid < SS){
        s_ear[tid] = expf(lAr[tid]);
        float sn, cs; sincosf(lAi[tid], &sn, &cs);
        s_cos[tid]=cs; s_sin[tid]=sn;
        s_db[tid] = dt_b[tid] + dt_bias[tid];
        s_pb[tid] = pg_b[tid];
    }
    __syncthreads();
    size_t idx = (size_t)blockIdx.x*256 + tid;      // over MM*SS
    int s = (int)(idx & 127);
    size_t m = idx >> 7;
    const float* row = &g_G1[m*N1];
    float z  = row[s] + s_db[s];
    float dt = (z > 20.f) ? z : log1pf(expf(z));
    float bxr = row[128+s], bxi = row[256+s];
    float pz  = row[384+s] + s_pb[s];
    float p   = 1.f/(1.f+expf(-pz));
    float am  = expf(-dt * s_ear[s]);
    float omp = 1.f - p;
    float Ar = p + omp*am*s_cos[s];
    float Ai = omp*am*s_sin[s];
    float sc = omp*dt;
    g_ABx[idx] = make_float4(Ar, Ai, bxr*sc, bxi*sc);
}

// ---------------- chunked scan ----------------
__global__ void scan_a(){
    int b = blockIdx.x >> 6;
    int c = blockIdx.x & (NC-1);
    int s = threadIdx.x;
    size_t base = ((size_t)b*LL + (size_t)c*CHUNK)*SS + s;
    float hr=0.f, hi=0.f, pr=1.f, pi=0.f;
    #pragma unroll 4
    for (int i=0;i<CHUNK;i++){
        float4 v = g_ABx[base + (size_t)i*SS];
        float nhr = v.x*hr - v.y*hi + v.z;
        float nhi = v.x*hi + v.y*hr + v.w;
        float npr = v.x*pr - v.y*pi;
        float npi = v.x*pi + v.y*pr;
        hr=nhr; hi=nhi; pr=npr; pi=npi;
    }
    int o = (b*NC + c)*SS + s;
    g_cA[o] = make_float2(pr,pi);
    g_cH[o] = make_float2(hr,hi);
}

__global__ void scan_b(){
    int tid = threadIdx.x;            // 512 = BB*SS
    int b = tid >> 7, s = tid & 127;
    float cr=0.f, ci=0.f;
    for (int c=0;c<NC;c++){
        int o = (b*NC + c)*SS + s;
        g_carry[o] = make_float2(cr,ci);
        float2 a = g_cA[o]; float2 h = g_cH[o];
        float nr  = a.x*cr - a.y*ci + h.x;
        float ni2 = a.x*ci + a.y*cr + h.y;
        cr=nr; ci=ni2;
    }
}

__global__ void scan_c(float* __restrict__ out){
    int b = blockIdx.x >> 6;
    int c = blockIdx.x & (NC-1);
    int s = threadIdx.x;
    int o = (b*NC + c)*SS + s;
    float2 cc = g_carry[o];
    float hr = cc.x, hi = cc.y;
    size_t base  = ((size_t)b*LL + (size_t)c*CHUNK)*SS + s;
    size_t mbase = (size_t)b*LL + (size_t)c*CHUNK;
    for (int i=0;i<CHUNK;i++){
        float4 v = g_ABx[base + (size_t)i*SS];
        float nhr = v.x*hr - v.y*hi + v.z;
        float nhi = v.x*hi + v.y*hr + v.w;
        hr=nhr; hi=nhi;
        size_t m = mbase + i;
        g_Hh[m*K2 + s]       = __float2half_rn(hr);
        g_Hh[m*K2 + 128 + s] = __float2half_rn(hi);
    }
    if (c == NC-1){
        out[(size_t)MM*N2 + (b*SS + s)*2 + 0] = hr;
        out[(size_t)MM*N2 + (b*SS + s)*2 + 1] = hi;
    }
}

// ---------------- GEMM2: y = [hr|hi] @ W2 + cmul(D,x) ----------------
// grid: blockIdx = mt*32 + nt. 128 threads, 4 warps 64x64.
__global__ __launch_bounds__(128,2) void gemm2(const float* __restrict__ x,
                                               const float* __restrict__ Dp,
                                               float* __restrict__ out){
    __shared__ __half As[2][TSZ];
    __shared__ __half Bs[2][TSZ];
    const int tid = threadIdx.x, lane = tid & 31, warp = tid >> 5;
    const int nt = blockIdx.x & 31, mt = blockIdx.x >> 5;
    const int KT = K2/32;   // 8
    const int wm = (warp >> 1) * 64, wn = (warp & 1) * 64;

    const __half* Ag = g_Hh  + (size_t)(mt*128 + tid)*K2;
    const __half* Bg = g_W2h + (size_t)(nt*128 + tid)*K2;
    const uint32_t sA = smem_u32(As), sB = smem_u32(Bs);
    const uint32_t dA = sA + tid*80, dB = sB + tid*80;

    const int arow = (lane & 7) + ((lane >> 3) & 1) * 8;
    const int acol = (lane >> 4) * 8;
    const int brow = (lane & 7) + (lane >> 4) * 8;
    const int bcol = ((lane >> 3) & 1) * 8;
    const uint32_t aoff = sA + ((wm + arow)*TPAD + acol)*2;
    const uint32_t boff = sB + ((wn + brow)*TPAD + bcol)*2;

    float acc[4][8][4];
    #pragma unroll
    for (int mi=0;mi<4;mi++)
        #pragma unroll
        for (int ni=0;ni<8;ni++){ acc[mi][ni][0]=0.f; acc[mi][ni][1]=0.f; acc[mi][ni][2]=0.f; acc[mi][ni][3]=0.f; }

    auto ISSUE = [&](int kt, int buf){
        const __half* a = Ag + kt*32;
        const __half* b = Bg + kt*32;
        uint32_t da = dA + buf*(TSZ*2), db = dB + buf*(TSZ*2);
        #pragma unroll
        for (int s=0;s<4;s++){
            CP16(da + s*16, a + s*8);
            CP16(db + s*16, b + s*8);
        }
        CPCOMMIT();
    };
    auto COMPUTE = [&](int buf){
        const uint32_t ab = aoff + buf*(TSZ*2);
        const uint32_t bb = boff + buf*(TSZ*2);
        #pragma unroll
        for (int ks=0; ks<2; ks++){
            const uint32_t kb2 = ks*32;
            unsigned af[4][4], bf[4][4];
            #pragma unroll
            for (int mi=0;mi<4;mi++)
                ldsm4(af[mi][0],af[mi][1],af[mi][2],af[mi][3], ab + mi*16*TPAD*2 + kb2);
            #pragma unroll
            for (int np=0;np<4;np++)
                ldsm4(bf[np][0],bf[np][1],bf[np][2],bf[np][3], bb + np*16*TPAD*2 + kb2);
            #pragma unroll
            for (int mi=0;mi<4;mi++)
                #pragma unroll
                for (int ni=0;ni<8;ni++){
                    unsigned bx[2] = { bf[ni>>1][(ni&1)*2], bf[ni>>1][(ni&1)*2+1] };
                    mma16(acc[mi][ni], af[mi], bx);
                }
        }
    };

    ISSUE(0, 0);
    int buf = 0;
    for (int kt=0; kt<KT; kt++){
        CPWAIT0();
        __syncthreads();
        if (kt+1 < KT) ISSUE(kt+1, buf^1);
        COMPUTE(buf);
        buf ^= 1;
    }

    const int g = lane >> 2, t = lane & 3;
    #pragma unroll
    for (int mi=0;mi<4;mi++){
        int row = mt*128 + wm + mi*16 + g;
        #pragma unroll
        for (int ni=0;ni<8;ni++){
            int ncol = nt*128 + wn + ni*8 + t*2;   // even
            int d = ncol >> 1;
            float2 Dv  = *reinterpret_cast<const float2*>(&Dp[d*2]);
            float2 xv0 = *reinterpret_cast<const float2*>(&x[((size_t)row*DIMM + d)*2]);
            float2 xv1 = *reinterpret_cast<const float2*>(&x[((size_t)(row+8)*DIMM + d)*2]);
            float y00 = acc[mi][ni][0] + Dv.x*xv0.x - Dv.y*xv0.y;
            float y01 = acc[mi][ni][1] + Dv.x*xv0.y + Dv.y*xv0.x;
            float y10 = acc[mi][ni][2] + Dv.x*xv1.x - Dv.y*xv1.y;
            float y11 = acc[mi][ni][3] + Dv.x*xv1.y + Dv.y*xv1.x;
            *reinterpret_cast<float2*>(&out[(size_t)row*N2 + ncol])     = make_float2(y00,y01);
            *reinterpret_cast<float2*>(&out[(size_t)(row+8)*N2 + ncol]) = make_float2(y10,y11);
        }
    }
}

// ---------------- launch ----------------
extern "C" void kernel_launch(void* const* d_in, const int* in_sizes, int n_in,
                              void* d_out, int out_size){
    const float* x       = (const float*)d_in[0];
    const float* lAr     = (const float*)d_in[1];
    const float* lAi     = (const float*)d_in[2];
    const float* Dp      = (const float*)d_in[3];
    const float* dt_w    = (const float*)d_in[4];
    const float* dt_b    = (const float*)d_in[5];
    const float* dt_bias = (const float*)d_in[6];
    const float* Br      = (const float*)d_in[7];
    const float* Bi      = (const float*)d_in[8];
    const float* Cr      = (const float*)d_in[9];
    const float* Ci      = (const float*)d_in[10];
    const float* pg_w    = (const float*)d_in[11];
    const float* pg_b    = (const float*)d_in[12];
    float* out = (float*)d_out;

    prep_ah<<<(int)(((size_t)MM*DIMM)/256), 256>>>(x);
    prep_w1h<<<(int)(((size_t)N1*K1)/256), 256>>>(dt_w, Br, Bi, pg_w);
    prep_w2h<<<(int)(((size_t)N2*K2)/256), 256>>>(Cr, Ci);
    gemm1<<<(MM/128)*4, 128>>>();
    ew1<<<(MM*SS)/256, 256>>>(dt_b, dt_bias, lAr, lAi, pg_b);
    scan_a<<<BB*NC, SS>>>();
    scan_b<<<1, BB*SS>>>();
    scan_c<<<BB*NC, SS>>>(out);
    gemm2<<<(MM/128)*32, 128>>>(x, Dp, out);
}

// round 14
// speedup vs baseline: 2.8155x; 1.1507x over previous
#include <cuda_runtime.h>
#include <cuda_fp16.h>
#include <cstdint>
#include <cstddef>

// Problem dims
#define BB   4
#define LL   4096
#define DIMM 2048
#define SS   128
#define MM   (BB*LL)        // 16384 token rows
#define N1   512            // dt | Bx_re | Bx_im | pg
#define K1   6144           // xr(2048) | xi(2048) | cab(2048)
#define K2   256            // hr(128) | hi(128)
#define N2   4096           // interleaved (yr,yi) per d
#define NC   64             // scan chunks per lane
#define CHUNK (LL/NC)       // 64

// SMEM staging: 128 rows x 32 k halves per stage, padded to 40 halves/row
// (80 B = 20 banks; (20r+t) mod 32 covers all banks -> conflict-free ldmatrix)
#define TPAD    40
#define TSTAGE  (128*TPAD*2)        // bytes per tile stage (10240)
#define STAGES  4
#define SMEM_BYTES (2*STAGES*TSTAGE) // A stages then B stages (81920)

// -------- scratch (__device__ globals; no allocations allowed) --------
__device__ __half g_Ah[(size_t)MM*K1];      // fp16 A operand: [xr|xi|cab] per row
__device__ __half g_W1h[(size_t)N1*K1];     // GEMM1 B operand, [n][k], fp16
__device__ __half g_W2h[(size_t)N2*K2];     // GEMM2 B operand, [n][k], fp16
__device__ float  g_G1[(size_t)MM*N1];      // GEMM1 fp32 outputs
__device__ float4 g_ABx[(size_t)MM*SS];     // {Ar,Ai,Bxr,Bxi} per (m,s)
__device__ float2 g_cA[BB*NC*SS];           // chunk A-products
__device__ float2 g_cH[BB*NC*SS];           // chunk local h_end
__device__ float2 g_carry[BB*NC*SS];        // per-chunk carry-in
__device__ __half g_Hh[(size_t)MM*K2];      // [hr|hi] rows, fp16, for GEMM2

__device__ __forceinline__ void mma16(float* c, const unsigned* a, const unsigned* b){
    asm volatile(
        "mma.sync.aligned.m16n8k16.row.col.f32.f16.f16.f32 "
        "{%0,%1,%2,%3}, {%4,%5,%6,%7}, {%8,%9}, {%0,%1,%2,%3};\n"
        : "+f"(c[0]), "+f"(c[1]), "+f"(c[2]), "+f"(c[3])
        : "r"(a[0]), "r"(a[1]), "r"(a[2]), "r"(a[3]), "r"(b[0]), "r"(b[1]));
}
__device__ __forceinline__ void ldsm4(unsigned& r0, unsigned& r1, unsigned& r2, unsigned& r3,
                                      uint32_t addr){
    asm volatile("ldmatrix.sync.aligned.m8n8.x4.shared.b16 {%0,%1,%2,%3}, [%4];"
        : "=r"(r0), "=r"(r1), "=r"(r2), "=r"(r3) : "r"(addr));
}
__device__ __forceinline__ uint32_t smem_u32(const void* p){
    uint32_t a;
    asm("{ .reg .u64 t; cvta.to.shared.u64 t, %1; cvt.u32.u64 %0, t; }" : "=r"(a) : "l"(p));
    return a;
}
#define CP16(dst, src) \
    asm volatile("cp.async.cg.shared.global [%0], [%1], 16;" :: "r"(dst), "l"(src))
#define CPCOMMIT() asm volatile("cp.async.commit_group;" ::: "memory")
#define CPWAIT2()  asm volatile("cp.async.wait_group 2;" ::: "memory")

extern __shared__ char smx[];

// ---------------- prep: fp16 A operand [xr | xi | cab] ----------------
__global__ void prep_ah(const float* __restrict__ x){
    size_t idx = (size_t)blockIdx.x*256 + threadIdx.x;   // over MM*DIMM
    size_t m = idx >> 11;
    int d = (int)(idx & 2047);
    float2 v = reinterpret_cast<const float2*>(x)[idx];
    __half* row = g_Ah + m*K1;
    row[d]        = __float2half_rn(v.x);
    row[2048 + d] = __float2half_rn(v.y);
    row[4096 + d] = __float2half_rn(sqrtf(v.x*v.x + v.y*v.y));
}

// ---------------- weight packing ([n][k] fp16) ----------------
__global__ void prep_w1h(const float* __restrict__ dt_w, const float* __restrict__ Br,
                         const float* __restrict__ Bi,   const float* __restrict__ pg_w){
    size_t idx = (size_t)blockIdx.x*256 + threadIdx.x;   // over N1*K1, k fast
    int n = (int)(idx / K1);
    int k = (int)(idx - (size_t)n*K1);
    float v = 0.f;
    if (n < 128) {
        if (k < 4096) v = dt_w[(size_t)n*4096 + k];
    } else if (n < 256) {
        int s = n - 128;
        if (k < 2048)       v =  Br[(size_t)k*SS + s];
        else if (k < 4096)  v = -Bi[(size_t)(k-2048)*SS + s];
    } else if (n < 384) {
        int s = n - 256;
        if (k < 2048)       v =  Bi[(size_t)k*SS + s];
        else if (k < 4096)  v =  Br[(size_t)(k-2048)*SS + s];
    } else {
        int s = n - 384;
        if (k >= 4096)      v =  pg_w[(size_t)s*DIMM + (k-4096)];
    }
    g_W1h[idx] = __float2half_rn(v);
}

__global__ void prep_w2h(const float* __restrict__ Cr, const float* __restrict__ Ci){
    size_t idx = (size_t)blockIdx.x*256 + threadIdx.x;   // over N2*K2, k fast
    int n = (int)(idx >> 8);
    int k = (int)(idx & 255);
    int d = n >> 1, c = n & 1;
    float v;
    if (k < 128) v = c ? Ci[(size_t)k*DIMM + d] : Cr[(size_t)k*DIMM + d];
    else { int s = k - 128; v = c ? Cr[(size_t)s*DIMM + d] : -Ci[(size_t)s*DIMM + d]; }
    g_W2h[idx] = __float2half_rn(v);
}

// ---------------- GEMM1: projections (4-stage cp.async + ldmatrix + HMMA) ----------------
// grid: blockIdx = mt*4 + nb; nb 0..2: K=[0,4096); nb==3: K=[4096,6144).
// 256 threads, 8 warps: warp tile 64m x 32n over 128x128 block tile.
__global__ __launch_bounds__(256,2) void gemm1(){
    const int tid = threadIdx.x, lane = tid & 31, warp = tid >> 5;
    const int nb = blockIdx.x & 3, mt = blockIdx.x >> 2;
    const int kstart = (nb < 3) ? 0 : 4096;
    const int KT     = (nb < 3) ? 128 : 64;
    const int wm = (warp & 1) * 64, wn = (warp >> 1) * 32;

    const uint32_t sb = smem_u32(smx);
    const int ldrow = tid >> 1, ldseg = (tid & 1);
    const __half* Ag = g_Ah  + (size_t)(mt*128 + ldrow)*K1 + kstart + ldseg*16;
    const __half* Bg = g_W1h + (size_t)(nb*128 + ldrow)*K1 + kstart + ldseg*16;
    const uint32_t dA = sb + ldrow*80 + ldseg*32;
    const uint32_t dB = dA + STAGES*TSTAGE;

    const int arow = (lane & 7) + ((lane >> 3) & 1) * 8;
    const int acol = (lane >> 4) * 8;
    const int brow = (lane & 7) + (lane >> 4) * 8;
    const int bcol = ((lane >> 3) & 1) * 8;
    const uint32_t aoff = sb + ((wm + arow)*TPAD + acol)*2;
    const uint32_t boff = sb + STAGES*TSTAGE + ((wn + brow)*TPAD + bcol)*2;

    float acc[4][4][4];
    #pragma unroll
    for (int mi=0;mi<4;mi++)
        #pragma unroll
        for (int ni=0;ni<4;ni++){ acc[mi][ni][0]=0.f; acc[mi][ni][1]=0.f; acc[mi][ni][2]=0.f; acc[mi][ni][3]=0.f; }

    auto ISSUE = [&](int kt, int st){
        const __half* a = Ag + kt*32;
        const __half* b = Bg + kt*32;
        const uint32_t da = dA + st*TSTAGE, db = dB + st*TSTAGE;
        CP16(da,      a);
        CP16(da + 16, a + 8);
        CP16(db,      b);
        CP16(db + 16, b + 8);
        CPCOMMIT();
    };
    auto COMPUTE = [&](int st){
        const uint32_t ab = aoff + st*TSTAGE;
        const uint32_t bb = boff + st*TSTAGE;
        #pragma unroll
        for (int ks=0; ks<2; ks++){
            const uint32_t kb2 = ks*32;   // 16 halves * 2B
            unsigned af[4][4], bf[2][4];
            #pragma unroll
            for (int mi=0;mi<4;mi++)
                ldsm4(af[mi][0],af[mi][1],af[mi][2],af[mi][3], ab + mi*16*80 + kb2);
            #pragma unroll
            for (int np=0;np<2;np++)
                ldsm4(bf[np][0],bf[np][1],bf[np][2],bf[np][3], bb + np*16*80 + kb2);
            #pragma unroll
            for (int mi=0;mi<4;mi++)
                #pragma unroll
                for (int ni=0;ni<4;ni++){
                    unsigned bx[2] = { bf[ni>>1][(ni&1)*2], bf[ni>>1][(ni&1)*2+1] };
                    mma16(acc[mi][ni], af[mi], bx);
                }
        }
    };

    #pragma unroll
    for (int s=0; s<STAGES-1; s++) ISSUE(s, s);
    for (int kt=0; kt<KT; kt++){
        CPWAIT2();
        __syncthreads();
        const int nx = kt + STAGES-1;
        if (nx < KT) ISSUE(nx, nx & (STAGES-1)); else CPCOMMIT();
        COMPUTE(kt & (STAGES-1));
    }

    const int g = lane >> 2, t = lane & 3;
    #pragma unroll
    for (int mi=0;mi<4;mi++){
        int row = mt*128 + wm + mi*16 + g;
        #pragma unroll
        for (int ni=0;ni<4;ni++){
            int col = nb*128 + wn + ni*8 + t*2;
            *reinterpret_cast<float2*>(&g_G1[(size_t)row*N1 + col])     = make_float2(acc[mi][ni][0], acc[mi][ni][1]);
            *reinterpret_cast<float2*>(&g_G1[(size_t)(row+8)*N1 + col]) = make_float2(acc[mi][ni][2], acc[mi][ni][3]);
        }
    }
}

// ---------------- elementwise: build A, Bx ----------------
__global__ void ew1(const float* __restrict__ dt_b, const float* __restrict__ dt_bias,
                    const float* __restrict__ lAr,  const float* __restrict__ lAi,
                    const float* __restrict__ pg_b){
    __shared__ float s_ear[SS], s_cos[SS], s_sin[SS], s_db[SS], s_pb[SS];
    int tid = threadIdx.x;
    if (tid < SS){
        s_ear[tid] = expf(lAr[tid]);
        float sn, cs; sincosf(lAi[tid], &sn, &cs);
        s_cos[tid]=cs; s_sin[tid]=sn;
        s_db[tid] = dt_b[tid] + dt_bias[tid];
        s_pb[tid] = pg_b[tid];
    }
    __syncthreads();
    size_t idx = (size_t)blockIdx.x*256 + tid;      // over MM*SS
    int s = (int)(idx & 127);
    size_t m = idx >> 7;
    const float* row = &g_G1[m*N1];
    float z  = row[s] + s_db[s];
    float dt = (z > 20.f) ? z : log1pf(expf(z));
    float bxr = row[128+s], bxi = row[256+s];
    float pz  = row[384+s] + s_pb[s];
    float p   = 1.f/(1.f+expf(-pz));
    float am  = expf(-dt * s_ear[s]);
    float omp = 1.f - p;
    float Ar = p + omp*am*s_cos[s];
    float Ai = omp*am*s_sin[s];
    float sc = omp*dt;
    g_ABx[idx] = make_float4(Ar, Ai, bxr*sc, bxi*sc);
}

// ---------------- chunked scan ----------------
__global__ void scan_a(){
    int b = blockIdx.x >> 6;
    int c = blockIdx.x & (NC-1);
    int s = threadIdx.x;
    size_t base = ((size_t)b*LL + (size_t)c*CHUNK)*SS + s;
    float hr=0.f, hi=0.f, pr=1.f, pi=0.f;
    #pragma unroll 4
    for (int i=0;i<CHUNK;i++){
        float4 v = g_ABx[base + (size_t)i*SS];
        float nhr = v.x*hr - v.y*hi + v.z;
        float nhi = v.x*hi + v.y*hr + v.w;
        float npr = v.x*pr - v.y*pi;
        float npi = v.x*pi + v.y*pr;
        hr=nhr; hi=nhi; pr=npr; pi=npi;
    }
    int o = (b*NC + c)*SS + s;
    g_cA[o] = make_float2(pr,pi);
    g_cH[o] = make_float2(hr,hi);
}

__global__ void scan_b(){
    int tid = threadIdx.x;            // 512 = BB*SS
    int b = tid >> 7, s = tid & 127;
    float cr=0.f, ci=0.f;
    for (int c=0;c<NC;c++){
        int o = (b*NC + c)*SS + s;
        g_carry[o] = make_float2(cr,ci);
        float2 a = g_cA[o]; float2 h = g_cH[o];
        float nr  = a.x*cr - a.y*ci + h.x;
        float ni2 = a.x*ci + a.y*cr + h.y;
        cr=nr; ci=ni2;
    }
}

__global__ void scan_c(float* __restrict__ out){
    int b = blockIdx.x >> 6;
    int c = blockIdx.x & (NC-1);
    int s = threadIdx.x;
    int o = (b*NC + c)*SS + s;
    float2 cc = g_carry[o];
    float hr = cc.x, hi = cc.y;
    size_t base  = ((size_t)b*LL + (size_t)c*CHUNK)*SS + s;
    size_t mbase = (size_t)b*LL + (size_t)c*CHUNK;
    for (int i=0;i<CHUNK;i++){
        float4 v = g_ABx[base + (size_t)i*SS];
        float nhr = v.x*hr - v.y*hi + v.z;
        float nhi = v.x*hi + v.y*hr + v.w;
        hr=nhr; hi=nhi;
        size_t m = mbase + i;
        g_Hh[m*K2 + s]       = __float2half_rn(hr);
        g_Hh[m*K2 + 128 + s] = __float2half_rn(hi);
    }
    if (c == NC-1){
        out[(size_t)MM*N2 + (b*SS + s)*2 + 0] = hr;
        out[(size_t)MM*N2 + (b*SS + s)*2 + 1] = hi;
    }
}

// ---------------- GEMM2: y = [hr|hi] @ W2 + cmul(D,x) ----------------
// grid: blockIdx = mt*32 + nt. 256 threads, 8 warps, warp tile 64x32.
__global__ __launch_bounds__(256,2) void gemm2(const float* __restrict__ x,
                                               const float* __restrict__ Dp,
                                               float* __restrict__ out){
    const int tid = threadIdx.x, lane = tid & 31, warp = tid >> 5;
    const int nt = blockIdx.x & 31, mt = blockIdx.x >> 5;
    const int KT = K2/32;   // 8
    const int wm = (warp & 1) * 64, wn = (warp >> 1) * 32;

    const uint32_t sb = smem_u32(smx);
    const int ldrow = tid >> 1, ldseg = (tid & 1);
    const __half* Ag = g_Hh  + (size_t)(mt*128 + ldrow)*K2 + ldseg*16;
    const __half* Bg = g_W2h + (size_t)(nt*128 + ldrow)*K2 + ldseg*16;
    const uint32_t dA = sb + ldrow*80 + ldseg*32;
    const uint32_t dB = dA + STAGES*TSTAGE;

    const int arow = (lane & 7) + ((lane >> 3) & 1) * 8;
    const int acol = (lane >> 4) * 8;
    const int brow = (lane & 7) + (lane >> 4) * 8;
    const int bcol = ((lane >> 3) & 1) * 8;
    const uint32_t aoff = sb + ((wm + arow)*TPAD + acol)*2;
    const uint32_t boff = sb + STAGES*TSTAGE + ((wn + brow)*TPAD + bcol)*2;

    float acc[4][4][4];
    #pragma unroll
    for (int mi=0;mi<4;mi++)
        #pragma unroll
        for (int ni=0;ni<4;ni++){ acc[mi][ni][0]=0.f; acc[mi][ni][1]=0.f; acc[mi][ni][2]=0.f; acc[mi][ni][3]=0.f; }

    auto ISSUE = [&](int kt, int st){
        const __half* a = Ag + kt*32;
        const __half* b = Bg + kt*32;
        const uint32_t da = dA + st*TSTAGE, db = dB + st*TSTAGE;
        CP16(da,      a);
        CP16(da + 16, a + 8);
        CP16(db,      b);
        CP16(db + 16, b + 8);
        CPCOMMIT();
    };
    auto COMPUTE = [&](int st){
        const uint32_t ab = aoff + st*TSTAGE;
        const uint32_t bb = boff + st*TSTAGE;
        #pragma unroll
        for (int ks=0; ks<2; ks++){
            const uint32_t kb2 = ks*32;
            unsigned af[4][4], bf[2][4];
            #pragma unroll
            for (int mi=0;mi<4;mi++)
                ldsm4(af[mi][0],af[mi][1],af[mi][2],af[mi][3], ab + mi*16*80 + kb2);
            #pragma unroll
            for (int np=0;np<2;np++)
                ldsm4(bf[np][0],bf[np][1],bf[np][2],bf[np][3], bb + np*16*80 + kb2);
            #pragma unroll
            for (int mi=0;mi<4;mi++)
                #pragma unroll
                for (int ni=0;ni<4;ni++){
                    unsigned bx[2] = { bf[ni>>1][(ni&1)*2], bf[ni>>1][(ni&1)*2+1] };
                    mma16(acc[mi][ni], af[mi], bx);
                }
        }
    };

    #pragma unroll
    for (int s=0; s<STAGES-1; s++) ISSUE(s, s);
    for (int kt=0; kt<KT; kt++){
        CPWAIT2();
        __syncthreads();
        const int nx = kt + STAGES-1;
        if (nx < KT) ISSUE(nx, nx & (STAGES-1)); else CPCOMMIT();
        COMPUTE(kt & (STAGES-1));
    }

    const int g = lane >> 2, t = lane & 3;
    #pragma unroll
    for (int mi=0;mi<4;mi++){
        int row = mt*128 + wm + mi*16 + g;
        #pragma unroll
        for (int ni=0;ni<4;ni++){
            int ncol = nt*128 + wn + ni*8 + t*2;   // even
            int d = ncol >> 1;
            float2 Dv  = *reinterpret_cast<const float2*>(&Dp[d*2]);
            float2 xv0 = *reinterpret_cast<const float2*>(&x[((size_t)row*DIMM + d)*2]);
            float2 xv1 = *reinterpret_cast<const float2*>(&x[((size_t)(row+8)*DIMM + d)*2]);
            float y00 = acc[mi][ni][0] + Dv.x*xv0.x - Dv.y*xv0.y;
            float y01 = acc[mi][ni][1] + Dv.x*xv0.y + Dv.y*xv0.x;
            float y10 = acc[mi][ni][2] + Dv.x*xv1.x - Dv.y*xv1.y;
            float y11 = acc[mi][ni][3] + Dv.x*xv1.y + Dv.y*xv1.x;
            *reinterpret_cast<float2*>(&out[(size_t)row*N2 + ncol])     = make_float2(y00,y01);
            *reinterpret_cast<float2*>(&out[(size_t)(row+8)*N2 + ncol]) = make_float2(y10,y11);
        }
    }
}

// ---------------- launch ----------------
extern "C" void kernel_launch(void* const* d_in, const int* in_sizes, int n_in,
                              void* d_out, int out_size){
    const float* x       = (const float*)d_in[0];
    const float* lAr     = (const float*)d_in[1];
    const float* lAi     = (const float*)d_in[2];
    const float* Dp      = (const float*)d_in[3];
    const float* dt_w    = (const float*)d_in[4];
    const float* dt_b    = (const float*)d_in[5];
    const float* dt_bias = (const float*)d_in[6];
    const float* Br      = (const float*)d_in[7];
    const float* Bi      = (const float*)d_in[8];
    const float* Cr      = (const float*)d_in[9];
    const float* Ci      = (const float*)d_in[10];
    const float* pg_w    = (const float*)d_in[11];
    const float* pg_b    = (const float*)d_in[12];
    float* out = (float*)d_out;

    cudaFuncSetAttribute(gemm1, cudaFuncAttributeMaxDynamicSharedMemorySize, SMEM_BYTES);
    cudaFuncSetAttribute(gemm2, cudaFuncAttributeMaxDynamicSharedMemorySize, SMEM_BYTES);

    prep_ah<<<(int)(((size_t)MM*DIMM)/256), 256>>>(x);
    prep_w1h<<<(int)(((size_t)N1*K1)/256), 256>>>(dt_w, Br, Bi, pg_w);
    prep_w2h<<<(int)(((size_t)N2*K2)/256), 256>>>(Cr, Ci);
    gemm1<<<(MM/128)*4, 256, SMEM_BYTES>>>();
    ew1<<<(MM*SS)/256, 256>>>(dt_b, dt_bias, lAr, lAi, pg_b);
    scan_a<<<BB*NC, SS>>>();
    scan_b<<<1, BB*SS>>>();
    scan_c<<<BB*NC, SS>>>(out);
    gemm2<<<(MM/128)*32, 256, SMEM_BYTES>>>(x, Dp, out);
}

// round 15
// speedup vs baseline: 2.8235x; 1.0029x over previous
#include <cuda_runtime.h>
#include <cuda_fp16.h>
#include <cstdint>
#include <cstddef>

// Problem dims
#define BB   4
#define LL   4096
#define DIMM 2048
#define SS   128
#define MM   (BB*LL)        // 16384 token rows
#define N1   512            // dt | Bx_re | Bx_im | pg
#define K1   6144           // xr(2048) | xi(2048) | cab(2048)
#define K2   256            // hr(128) | hi(128)
#define N2   4096           // interleaved (yr,yi) per d
#define NC   64             // scan chunks per lane
#define CHUNK (LL/NC)       // 64

// SMEM staging: 128 rows x 32 k halves per stage, padded to 40 halves/row
// (80 B = 20 banks; (20r+t) mod 32 covers all banks -> conflict-free ldmatrix)
#define TPAD    40
#define TSTAGE  (128*TPAD*2)        // bytes per tile stage (10240)
#define STAGES  4
#define SMEM_BYTES (2*STAGES*TSTAGE) // A stages then B stages (81920)

// -------- scratch (__device__ globals; no allocations allowed) --------
__device__ __half g_Ah[(size_t)MM*K1];      // fp16 A operand: [xr|xi|cab] per row
__device__ __half g_W1h[(size_t)N1*K1];     // GEMM1 B operand, [n][k], fp16
__device__ __half g_W2h[(size_t)N2*K2];     // GEMM2 B operand, [n][k], fp16
__device__ float  g_G1[(size_t)MM*N1];      // GEMM1 fp32 outputs
__device__ float4 g_ABx[(size_t)MM*SS];     // {Ar,Ai,Bxr,Bxi} per (m,s)
__device__ float2 g_cA[BB*NC*SS];           // chunk A-products
__device__ float2 g_cH[BB*NC*SS];           // chunk local h_end
__device__ float2 g_carry[BB*NC*SS];        // per-chunk carry-in
__device__ __half g_Hh[(size_t)MM*K2];      // [hr|hi] rows, fp16, for GEMM2

__device__ __forceinline__ void mma16(float* c, const unsigned* a, const unsigned* b){
    asm volatile(
        "mma.sync.aligned.m16n8k16.row.col.f32.f16.f16.f32 "
        "{%0,%1,%2,%3}, {%4,%5,%6,%7}, {%8,%9}, {%0,%1,%2,%3};\n"
        : "+f"(c[0]), "+f"(c[1]), "+f"(c[2]), "+f"(c[3])
        : "r"(a[0]), "r"(a[1]), "r"(a[2]), "r"(a[3]), "r"(b[0]), "r"(b[1]));
}
__device__ __forceinline__ void ldsm4(unsigned& r0, unsigned& r1, unsigned& r2, unsigned& r3,
                                      uint32_t addr){
    asm volatile("ldmatrix.sync.aligned.m8n8.x4.shared.b16 {%0,%1,%2,%3}, [%4];"
        : "=r"(r0), "=r"(r1), "=r"(r2), "=r"(r3) : "r"(addr));
}
__device__ __forceinline__ uint32_t smem_u32(const void* p){
    uint32_t a;
    asm("{ .reg .u64 t; cvta.to.shared.u64 t, %1; cvt.u32.u64 %0, t; }" : "=r"(a) : "l"(p));
    return a;
}
#define CP16(dst, src) \
    asm volatile("cp.async.cg.shared.global [%0], [%1], 16;" :: "r"(dst), "l"(src))
#define CPCOMMIT() asm volatile("cp.async.commit_group;" ::: "memory")
#define CPWAIT2()  asm volatile("cp.async.wait_group 2;" ::: "memory")

extern __shared__ char smx[];

// ---------------- prep: fp16 A operand [xr | xi | cab] ----------------
__global__ void prep_ah(const float* __restrict__ x){
    size_t idx = (size_t)blockIdx.x*256 + threadIdx.x;   // over MM*DIMM
    size_t m = idx >> 11;
    int d = (int)(idx & 2047);
    float2 v = reinterpret_cast<const float2*>(x)[idx];
    __half* row = g_Ah + m*K1;
    row[d]        = __float2half_rn(v.x);
    row[2048 + d] = __float2half_rn(v.y);
    row[4096 + d] = __float2half_rn(sqrtf(v.x*v.x + v.y*v.y));
}

// ---------------- weight packing ([n][k] fp16) ----------------
__global__ void prep_w1h(const float* __restrict__ dt_w, const float* __restrict__ Br,
                         const float* __restrict__ Bi,   const float* __restrict__ pg_w){
    size_t idx = (size_t)blockIdx.x*256 + threadIdx.x;   // over N1*K1, k fast
    int n = (int)(idx / K1);
    int k = (int)(idx - (size_t)n*K1);
    float v = 0.f;
    if (n < 128) {
        if (k < 4096) v = dt_w[(size_t)n*4096 + k];
    } else if (n < 256) {
        int s = n - 128;
        if (k < 2048)       v =  Br[(size_t)k*SS + s];
        else if (k < 4096)  v = -Bi[(size_t)(k-2048)*SS + s];
    } else if (n < 384) {
        int s = n - 256;
        if (k < 2048)       v =  Bi[(size_t)k*SS + s];
        else if (k < 4096)  v =  Br[(size_t)(k-2048)*SS + s];
    } else {
        int s = n - 384;
        if (k >= 4096)      v =  pg_w[(size_t)s*DIMM + (k-4096)];
    }
    g_W1h[idx] = __float2half_rn(v);
}

__global__ void prep_w2h(const float* __restrict__ Cr, const float* __restrict__ Ci){
    size_t idx = (size_t)blockIdx.x*256 + threadIdx.x;   // over N2*K2, k fast
    int n = (int)(idx >> 8);
    int k = (int)(idx & 255);
    int d = n >> 1, c = n & 1;
    float v;
    if (k < 128) v = c ? Ci[(size_t)k*DIMM + d] : Cr[(size_t)k*DIMM + d];
    else { int s = k - 128; v = c ? Cr[(size_t)s*DIMM + d] : -Ci[(size_t)s*DIMM + d]; }
    g_W2h[idx] = __float2half_rn(v);
}

// ---------------- GEMM1: projections (4-stage cp.async + ldmatrix + HMMA) ----------------
// grid: blockIdx = mt*4 + nb; nb 0..2: K=[0,4096); nb==3: K=[4096,6144).
// 256 threads, 8 warps: warp tile 64m x 32n over 128x128 block tile.
__global__ __launch_bounds__(256,2) void gemm1(){
    const int tid = threadIdx.x, lane = tid & 31, warp = tid >> 5;
    const int nb = blockIdx.x & 3, mt = blockIdx.x >> 2;
    const int kstart = (nb < 3) ? 0 : 4096;
    const int KT     = (nb < 3) ? 128 : 64;
    const int wm = (warp & 1) * 64, wn = (warp >> 1) * 32;

    const uint32_t sb = smem_u32(smx);
    const int ldrow = tid >> 1, ldseg = (tid & 1);
    const __half* Ag = g_Ah  + (size_t)(mt*128 + ldrow)*K1 + kstart + ldseg*16;
    const __half* Bg = g_W1h + (size_t)(nb*128 + ldrow)*K1 + kstart + ldseg*16;
    const uint32_t dA = sb + ldrow*80 + ldseg*32;
    const uint32_t dB = dA + STAGES*TSTAGE;

    const int arow = (lane & 7) + ((lane >> 3) & 1) * 8;
    const int acol = (lane >> 4) * 8;
    const int brow = (lane & 7) + (lane >> 4) * 8;
    const int bcol = ((lane >> 3) & 1) * 8;
    const uint32_t aoff = sb + ((wm + arow)*TPAD + acol)*2;
    const uint32_t boff = sb + STAGES*TSTAGE + ((wn + brow)*TPAD + bcol)*2;

    float acc[4][4][4];
    #pragma unroll
    for (int mi=0;mi<4;mi++)
        #pragma unroll
        for (int ni=0;ni<4;ni++){ acc[mi][ni][0]=0.f; acc[mi][ni][1]=0.f; acc[mi][ni][2]=0.f; acc[mi][ni][3]=0.f; }

    auto ISSUE = [&](int kt, int st){
        const __half* a = Ag + kt*32;
        const __half* b = Bg + kt*32;
        const uint32_t da = dA + st*TSTAGE, db = dB + st*TSTAGE;
        CP16(da,      a);
        CP16(da + 16, a + 8);
        CP16(db,      b);
        CP16(db + 16, b + 8);
        CPCOMMIT();
    };
    auto COMPUTE = [&](int st){
        const uint32_t ab = aoff + st*TSTAGE;
        const uint32_t bb = boff + st*TSTAGE;
        #pragma unroll
        for (int ks=0; ks<2; ks++){
            const uint32_t kb2 = ks*32;   // 16 halves * 2B
            unsigned af[4][4], bf[2][4];
            #pragma unroll
            for (int mi=0;mi<4;mi++)
                ldsm4(af[mi][0],af[mi][1],af[mi][2],af[mi][3], ab + mi*16*80 + kb2);
            #pragma unroll
            for (int np=0;np<2;np++)
                ldsm4(bf[np][0],bf[np][1],bf[np][2],bf[np][3], bb + np*16*80 + kb2);
            #pragma unroll
            for (int mi=0;mi<4;mi++)
                #pragma unroll
                for (int ni=0;ni<4;ni++){
                    unsigned bx[2] = { bf[ni>>1][(ni&1)*2], bf[ni>>1][(ni&1)*2+1] };
                    mma16(acc[mi][ni], af[mi], bx);
                }
        }
    };

    #pragma unroll
    for (int s=0; s<STAGES-1; s++) ISSUE(s, s);
    for (int kt=0; kt<KT; kt++){
        CPWAIT2();
        __syncthreads();
        const int nx = kt + STAGES-1;
        if (nx < KT) ISSUE(nx, nx & (STAGES-1)); else CPCOMMIT();
        COMPUTE(kt & (STAGES-1));
    }

    const int g = lane >> 2, t = lane & 3;
    #pragma unroll
    for (int mi=0;mi<4;mi++){
        int row = mt*128 + wm + mi*16 + g;
        #pragma unroll
        for (int ni=0;ni<4;ni++){
            int col = nb*128 + wn + ni*8 + t*2;
            *reinterpret_cast<float2*>(&g_G1[(size_t)row*N1 + col])     = make_float2(acc[mi][ni][0], acc[mi][ni][1]);
            *reinterpret_cast<float2*>(&g_G1[(size_t)(row+8)*N1 + col]) = make_float2(acc[mi][ni][2], acc[mi][ni][3]);
        }
    }
}

// ---------------- elementwise: build A, Bx ----------------
__global__ void ew1(const float* __restrict__ dt_b, const float* __restrict__ dt_bias,
                    const float* __restrict__ lAr,  const float* __restrict__ lAi,
                    const float* __restrict__ pg_b){
    __shared__ float s_ear[SS], s_cos[SS], s_sin[SS], s_db[SS], s_pb[SS];
    int tid = threadIdx.x;
    if (tid < SS){
        s_ear[tid] = expf(lAr[tid]);
        float sn, cs; sincosf(lAi[tid], &sn, &cs);
        s_cos[tid]=cs; s_sin[tid]=sn;
        s_db[tid] = dt_b[tid] + dt_bias[tid];
        s_pb[tid] = pg_b[tid];
    }
    __syncthreads();
    size_t idx = (size_t)blockIdx.x*256 + tid;      // over MM*SS
    int s = (int)(idx & 127);
    size_t m = idx >> 7;
    const float* row = &g_G1[m*N1];
    float z  = row[s] + s_db[s];
    float dt = (z > 20.f) ? z : log1pf(expf(z));
    float bxr = row[128+s], bxi = row[256+s];
    float pz  = row[384+s] + s_pb[s];
    float p   = 1.f/(1.f+expf(-pz));
    float am  = expf(-dt * s_ear[s]);
    float omp = 1.f - p;
    float Ar = p + omp*am*s_cos[s];
    float Ai = omp*am*s_sin[s];
    float sc = omp*dt;
    g_ABx[idx] = make_float4(Ar, Ai, bxr*sc, bxi*sc);
}

// ---------------- chunked scan ----------------
__global__ void scan_a(){
    int b = blockIdx.x >> 6;
    int c = blockIdx.x & (NC-1);
    int s = threadIdx.x;
    size_t base = ((size_t)b*LL + (size_t)c*CHUNK)*SS + s;
    float hr=0.f, hi=0.f, pr=1.f, pi=0.f;
    #pragma unroll 4
    for (int i=0;i<CHUNK;i++){
        float4 v = g_ABx[base + (size_t)i*SS];
        float nhr = v.x*hr - v.y*hi + v.z;
        float nhi = v.x*hi + v.y*hr + v.w;
        float npr = v.x*pr - v.y*pi;
        float npi = v.x*pi + v.y*pr;
        hr=nhr; hi=nhi; pr=npr; pi=npi;
    }
    int o = (b*NC + c)*SS + s;
    g_cA[o] = make_float2(pr,pi);
    g_cH[o] = make_float2(hr,hi);
}

__global__ void scan_b(){
    int tid = threadIdx.x;            // 512 = BB*SS
    int b = tid >> 7, s = tid & 127;
    float cr=0.f, ci=0.f;
    for (int c=0;c<NC;c++){
        int o = (b*NC + c)*SS + s;
        g_carry[o] = make_float2(cr,ci);
        float2 a = g_cA[o]; float2 h = g_cH[o];
        float nr  = a.x*cr - a.y*ci + h.x;
        float ni2 = a.x*ci + a.y*cr + h.y;
        cr=nr; ci=ni2;
    }
}

__global__ void scan_c(float* __restrict__ out){
    int b = blockIdx.x >> 6;
    int c = blockIdx.x & (NC-1);
    int s = threadIdx.x;
    int o = (b*NC + c)*SS + s;
    float2 cc = g_carry[o];
    float hr = cc.x, hi = cc.y;
    size_t base  = ((size_t)b*LL + (size_t)c*CHUNK)*SS + s;
    size_t mbase = (size_t)b*LL + (size_t)c*CHUNK;
    for (int i=0;i<CHUNK;i++){
        float4 v = g_ABx[base + (size_t)i*SS];
        float nhr = v.x*hr - v.y*hi + v.z;
        float nhi = v.x*hi + v.y*hr + v.w;
        hr=nhr; hi=nhi;
        size_t m = mbase + i;
        g_Hh[m*K2 + s]       = __float2half_rn(hr);
        g_Hh[m*K2 + 128 + s] = __float2half_rn(hi);
    }
    if (c == NC-1){
        out[(size_t)MM*N2 + (b*SS + s)*2 + 0] = hr;
        out[(size_t)MM*N2 + (b*SS + s)*2 + 1] = hi;
    }
}

// ---------------- GEMM2: y = [hr|hi] @ W2 + cmul(D,x) ----------------
// grid: blockIdx = mt*32 + nt. 256 threads, 8 warps, warp tile 64x32.
__global__ __launch_bounds__(256,2) void gemm2(const float* __restrict__ x,
                                               const float* __restrict__ Dp,
                                               float* __restrict__ out){
    const int tid = threadIdx.x, lane = tid & 31, warp = tid >> 5;
    const int nt = blockIdx.x & 31, mt = blockIdx.x >> 5;
    const int KT = K2/32;   // 8
    const int wm = (warp & 1) * 64, wn = (warp >> 1) * 32;

    const uint32_t sb = smem_u32(smx);
    const int ldrow = tid >> 1, ldseg = (tid & 1);
    const __half* Ag = g_Hh  + (size_t)(mt*128 + ldrow)*K2 + ldseg*16;
    const __half* Bg = g_W2h + (size_t)(nt*128 + ldrow)*K2 + ldseg*16;
    const uint32_t dA = sb + ldrow*80 + ldseg*32;
    const uint32_t dB = dA + STAGES*TSTAGE;

    const int arow = (lane & 7) + ((lane >> 3) & 1) * 8;
    const int acol = (lane >> 4) * 8;
    const int brow = (lane & 7) + (lane >> 4) * 8;
    const int bcol = ((lane >> 3) & 1) * 8;
    const uint32_t aoff = sb + ((wm + arow)*TPAD + acol)*2;
    const uint32_t boff = sb + STAGES*TSTAGE + ((wn + brow)*TPAD + bcol)*2;

    float acc[4][4][4];
    #pragma unroll
    for (int mi=0;mi<4;mi++)
        #pragma unroll
        for (int ni=0;ni<4;ni++){ acc[mi][ni][0]=0.f; acc[mi][ni][1]=0.f; acc[mi][ni][2]=0.f; acc[mi][ni][3]=0.f; }

    auto ISSUE = [&](int kt, int st){
        const __half* a = Ag + kt*32;
        const __half* b = Bg + kt*32;
        const uint32_t da = dA + st*TSTAGE, db = dB + st*TSTAGE;
        CP16(da,      a);
        CP16(da + 16, a + 8);
        CP16(db,      b);
        CP16(db + 16, b + 8);
        CPCOMMIT();
    };
    auto COMPUTE = [&](int st){
        const uint32_t ab = aoff + st*TSTAGE;
        const uint32_t bb = boff + st*TSTAGE;
        #pragma unroll
        for (int ks=0; ks<2; ks++){
            const uint32_t kb2 = ks*32;
            unsigned af[4][4], bf[2][4];
            #pragma unroll
            for (int mi=0;mi<4;mi++)
                ldsm4(af[mi][0],af[mi][1],af[mi][2],af[mi][3], ab + mi*16*80 + kb2);
            #pragma unroll
            for (int np=0;np<2;np++)
                ldsm4(bf[np][0],bf[np][1],bf[np][2],bf[np][3], bb + np*16*80 + kb2);
            #pragma unroll
            for (int mi=0;mi<4;mi++)
                #pragma unroll
                for (int ni=0;ni<4;ni++){
                    unsigned bx[2] = { bf[ni>>1][(ni&1)*2], bf[ni>>1][(ni&1)*2+1] };
                    mma16(acc[mi][ni], af[mi], bx);
                }
        }
    };

    #pragma unroll
    for (int s=0; s<STAGES-1; s++) ISSUE(s, s);
    for (int kt=0; kt<KT; kt++){
        CPWAIT2();
        __syncthreads();
        const int nx = kt + STAGES-1;
        if (nx < KT) ISSUE(nx, nx & (STAGES-1)); else CPCOMMIT();
        COMPUTE(kt & (STAGES-1));
    }

    const int g = lane >> 2, t = lane & 3;
    #pragma unroll
    for (int mi=0;mi<4;mi++){
        int row = mt*128 + wm + mi*16 + g;
        #pragma unroll
        for (int ni=0;ni<4;ni++){
            int ncol = nt*128 + wn + ni*8 + t*2;   // even
            int d = ncol >> 1;
            float2 Dv  = *reinterpret_cast<const float2*>(&Dp[d*2]);
            float2 xv0 = *reinterpret_cast<const float2*>(&x[((size_t)row*DIMM + d)*2]);
            float2 xv1 = *reinterpret_cast<const float2*>(&x[((size_t)(row+8)*DIMM + d)*2]);
            float y00 = acc[mi][ni][0] + Dv.x*xv0.x - Dv.y*xv0.y;
            float y01 = acc[mi][ni][1] + Dv.x*xv0.y + Dv.y*xv0.x;
            float y10 = acc[mi][ni][2] + Dv.x*xv1.x - Dv.y*xv1.y;
            float y11 = acc[mi][ni][3] + Dv.x*xv1.y + Dv.y*xv1.x;
            *reinterpret_cast<float2*>(&out[(size_t)row*N2 + ncol])     = make_float2(y00,y01);
            *reinterpret_cast<float2*>(&out[(size_t)(row+8)*N2 + ncol]) = make_float2(y10,y11);
        }
    }
}

// ---------------- launch ----------------
extern "C" void kernel_launch(void* const* d_in, const int* in_sizes, int n_in,
                              void* d_out, int out_size){
    const float* x       = (const float*)d_in[0];
    const float* lAr     = (const float*)d_in[1];
    const float* lAi     = (const float*)d_in[2];
    const float* Dp      = (const float*)d_in[3];
    const float* dt_w    = (const float*)d_in[4];
    const float* dt_b    = (const float*)d_in[5];
    const float* dt_bias = (const float*)d_in[6];
    const float* Br      = (const float*)d_in[7];
    const float* Bi      = (const float*)d_in[8];
    const float* Cr      = (const float*)d_in[9];
    const float* Ci      = (const float*)d_in[10];
    const float* pg_w    = (const float*)d_in[11];
    const float* pg_b    = (const float*)d_in[12];
    float* out = (float*)d_out;

    cudaFuncSetAttribute(gemm1, cudaFuncAttributeMaxDynamicSharedMemorySize, SMEM_BYTES);
    cudaFuncSetAttribute(gemm2, cudaFuncAttributeMaxDynamicSharedMemorySize, SMEM_BYTES);

    prep_ah<<<(int)(((size_t)MM*DIMM)/256), 256>>>(x);
    prep_w1h<<<(int)(((size_t)N1*K1)/256), 256>>>(dt_w, Br, Bi, pg_w);
    prep_w2h<<<(int)(((size_t)N2*K2)/256), 256>>>(Cr, Ci);
    gemm1<<<(MM/128)*4, 256, SMEM_BYTES>>>();
    ew1<<<(MM*SS)/256, 256>>>(dt_b, dt_bias, lAr, lAi, pg_b);
    scan_a<<<BB*NC, SS>>>();
    scan_b<<<1, BB*SS>>>();
    scan_c<<<BB*NC, SS>>>(out);
    gemm2<<<(MM/128)*32, 256, SMEM_BYTES>>>(x, Dp, out);
}